// round 12
// baseline (speedup 1.0000x reference)
#include <cuda_runtime.h>
#include <cuda_bf16.h>
#include <math.h>
#include <stdint.h>

#define HW 128
#define NPIX 16384
#define BATCH 2
#define KJ 128
#define NPAIR 8128
#define NROWS (BATCH * NPAIR)   // 16256
#define DLOI 128
#define DFC 1024
#define MPIX (BATCH * NPIX)     // 32768

// ---------------- scratch (device globals; no allocations allowed) ----------
__device__ float g_xf[(size_t)MPIX * DLOI];   // (b*pix, d)
__device__ float g_xy[BATCH][KJ][2];
__device__ __align__(16) __nv_bfloat16 g_ft_hi[(size_t)MPIX * 256];
__device__ __align__(16) __nv_bfloat16 g_ft_lo[(size_t)MPIX * 256];
__device__ __align__(16) __nv_bfloat16 g_fc_hi[256 * 256];   // padded N: 128->256
__device__ __align__(16) __nv_bfloat16 g_fc_lo[256 * 256];
__device__ __align__(16) __nv_bfloat16 g_xv_hi[(size_t)NROWS * DFC];
__device__ __align__(16) __nv_bfloat16 g_xv_lo[(size_t)NROWS * DFC];
__device__ __align__(16) __nv_bfloat16 g_h1_hi[(size_t)NROWS * DFC];
__device__ __align__(16) __nv_bfloat16 g_h1_lo[(size_t)NROWS * DFC];
__device__ __align__(16) __nv_bfloat16 g_w1t_hi[DFC * DFC];
__device__ __align__(16) __nv_bfloat16 g_w1t_lo[DFC * DFC];
__device__ __align__(16) __nv_bfloat16 g_w2t_hi[DFC * DFC];
__device__ __align__(16) __nv_bfloat16 g_w2t_lo[DFC * DFC];
__device__ float g_part[(size_t)NROWS * 4];
__device__ unsigned int g_tilectr[3];

// ---------------- helpers ----------------------------------------------------
__device__ __forceinline__ uint32_t smem_u32(const void* p) {
    uint32_t a;
    asm("{ .reg .u64 t; cvta.to.shared.u64 t, %1; cvt.u32.u64 %0, t; }"
        : "=r"(a) : "l"(p));
    return a;
}
__device__ __forceinline__ void cp16(uint32_t s, const void* g) {
    asm volatile("cp.async.cg.shared.global [%0], [%1], 16;"
                 :: "r"(s), "l"(g) : "memory");
}
#define CP_COMMIT() asm volatile("cp.async.commit_group;" ::: "memory")
#define CP_WAIT(n)  asm volatile("cp.async.wait_group %0;" :: "n"(n) : "memory")

__device__ __forceinline__ void ldm_x4(uint32_t* r, uint32_t addr) {
    asm volatile("ldmatrix.sync.aligned.m8n8.x4.shared.b16 {%0,%1,%2,%3}, [%4];"
                 : "=r"(r[0]), "=r"(r[1]), "=r"(r[2]), "=r"(r[3]) : "r"(addr));
}
__device__ __forceinline__ void mma16816(float* c, const uint32_t* a,
                                         const uint32_t* b) {
    asm volatile(
        "mma.sync.aligned.m16n8k16.row.col.f32.bf16.bf16.f32 "
        "{%0,%1,%2,%3}, {%4,%5,%6,%7}, {%8,%9}, {%0,%1,%2,%3};"
        : "+f"(c[0]), "+f"(c[1]), "+f"(c[2]), "+f"(c[3])
        : "r"(a[0]), "r"(a[1]), "r"(a[2]), "r"(a[3]), "r"(b[0]), "r"(b[1]));
}

// ---------------- pair index helpers (triu_indices(K=128, k=1)) -------------
__device__ __forceinline__ int pair_off(int u) { return u * (255 - u) / 2; }
__device__ __forceinline__ void pair_uv(int p, int& u, int& v) {
    int uu = (int)((255.0 - sqrt(255.0 * 255.0 - 8.0 * (double)p)) * 0.5);
    if (uu < 0) uu = 0;
    if (uu > 126) uu = 126;
    while (uu < 126 && pair_off(uu + 1) <= p) uu++;
    while (uu > 0 && pair_off(uu) > p) uu--;
    u = uu;
    v = uu + 1 + (p - pair_off(uu));
}

// ---------------- K1: jmap + NMS + exact top-128 + junction coords ----------
__global__ void k_topk(const float* __restrict__ inputs) {
    extern __shared__ float sh[];
    float* smap = sh;
    float* nmsv = smap + NPIX;
    float* bv   = nmsv + NPIX;
    int*   bi   = (int*)(bv + 512);
    float* wv   = (float*)(bi + 512);
    int*   wi   = (int*)(wv + 16);
    int*   topidx = wi + 16;

    const int b = blockIdx.x;
    const int t = threadIdx.x;
    const float* in0 = inputs + (size_t)b * 5 * NPIX;
    const float* in1 = in0 + NPIX;

    for (int i = t; i < NPIX; i += 512) {
        float x0 = in0[i], x1 = in1[i];
        float m = fmaxf(x0, x1);
        float e0 = expf(x0 - m), e1 = expf(x1 - m);
        smap[i] = e1 / (e0 + e1);
    }
    __syncthreads();

    float bval = -1.0f;
    int bidx = t * 32;
    for (int j = 0; j < 32; j++) {
        int idx = t * 32 + j;
        int y = idx >> 7, x = idx & 127;
        float v = smap[idx];
        float m = v;
        #pragma unroll
        for (int dy = -1; dy <= 1; dy++) {
            int yy = y + dy;
            if (yy < 0 || yy >= HW) continue;
            #pragma unroll
            for (int dx = -1; dx <= 1; dx++) {
                int xx = x + dx;
                if (xx < 0 || xx >= HW) continue;
                m = fmaxf(m, smap[yy * HW + xx]);
            }
        }
        float nv = (v == m) ? v : 0.0f;
        nmsv[idx] = nv;
        if (nv > bval) { bval = nv; bidx = idx; }
    }
    bv[t] = bval; bi[t] = bidx;
    __syncthreads();

    for (int r = 0; r < KJ; r++) {
        float v = bv[t];
        int ix = bi[t];
        #pragma unroll
        for (int off = 16; off; off >>= 1) {
            float v2 = __shfl_down_sync(0xffffffffu, v, off);
            int   i2 = __shfl_down_sync(0xffffffffu, ix, off);
            if (v2 > v || (v2 == v && i2 < ix)) { v = v2; ix = i2; }
        }
        if ((t & 31) == 0) { wv[t >> 5] = v; wi[t >> 5] = ix; }
        __syncthreads();
        if (t < 32) {
            float v3 = (t < 16) ? wv[t] : -2.0f;
            int   i3 = (t < 16) ? wi[t] : 0x7fffffff;
            #pragma unroll
            for (int off = 8; off; off >>= 1) {
                float v2 = __shfl_down_sync(0xffffffffu, v3, off);
                int   i2 = __shfl_down_sync(0xffffffffu, i3, off);
                if (v2 > v3 || (v2 == v3 && i2 < i3)) { v3 = v2; i3 = i2; }
            }
            if (t == 0) topidx[r] = i3;
        }
        __syncthreads();
        int win = topidx[r];
        if (t == (win >> 5)) {
            nmsv[win] = -1.0f;
            float nb = -1.0f;
            int nbi = t * 32;
            for (int j = 0; j < 32; j++) {
                float nv = nmsv[t * 32 + j];
                if (nv > nb) { nb = nv; nbi = t * 32 + j; }
            }
            bv[t] = nb; bi[t] = nbi;
        }
        __syncthreads();
    }

    if (t < KJ) {
        int idx = topidx[t];
        const float* in3 = in0 + 3 * NPIX;
        const float* in4 = in0 + 4 * NPIX;
        float sy = 1.0f / (1.0f + expf(-in3[idx]));
        float sx = 1.0f / (1.0f + expf(-in4[idx]));
        g_xy[b][t][0] = (float)(idx >> 7) + sy;
        g_xy[b][t][1] = (float)(idx & 127) + sx;
    }
}

// ---------------- K2a: transpose+split features (c,pix)->(pix,c) bf16 -------
__global__ __launch_bounds__(256) void k_ftsplit(const float* __restrict__ F) {
    __shared__ float tile[32][33];
    const int tx = threadIdx.x & 31;
    const int ty = threadIdx.x >> 5;
    const int pixb = blockIdx.x * 32;
    const int cb = blockIdx.y * 32;
    const int b = blockIdx.z;
    const float* src = F + (size_t)b * 256 * NPIX;
    #pragma unroll
    for (int j = 0; j < 4; j++) {
        int cl = ty * 4 + j;
        tile[cl][tx] = src[(size_t)(cb + cl) * NPIX + pixb + tx];
    }
    __syncthreads();
    #pragma unroll
    for (int j = 0; j < 4; j++) {
        int pl = ty * 4 + j;
        float v = tile[tx][pl];
        __nv_bfloat16 h = __float2bfloat16(v);
        size_t o = ((size_t)b * NPIX + pixb + pl) * 256 + cb + tx;
        g_ft_hi[o] = h;
        g_ft_lo[o] = __float2bfloat16(v - __bfloat162float(h));
    }
}

// ---------------- K2b: split fc1_w, zero-pad N to 256 -----------------------
__global__ void k_fsplit(const float* __restrict__ W) {
    int i = blockIdx.x * 256 + threadIdx.x;
    if (i < 256 * 256) {
        if (i < DLOI * 256) {
            float v = W[i];
            __nv_bfloat16 h = __float2bfloat16(v);
            g_fc_hi[i] = h;
            g_fc_lo[i] = __float2bfloat16(v - __bfloat162float(h));
        } else {
            g_fc_hi[i] = __float2bfloat16(0.0f);
            g_fc_lo[i] = __float2bfloat16(0.0f);
        }
    }
}

// ---------------- K3: LOI pool (float4 gathers) --> xv bf16 hi/lo -----------
__global__ __launch_bounds__(128) void k_pool() {
    const int gp = blockIdx.x;
    const int b = gp / NPAIR;
    const int p = gp - b * NPAIR;
    const int t = threadIdx.x;

    __shared__ __align__(16) int   s_o[32][4];
    __shared__ __align__(16) float s_w[32][4];
    __shared__ __align__(16) float stage2[8 * 132];

    if (t < 32) {
        int u, v;
        pair_uv(p, u, v);
        const float yu = g_xy[b][u][0], xu = g_xy[b][u][1];
        const float yv = g_xy[b][v][0], xv = g_xy[b][v][1];
        const int j = t;
        float lam = (float)j / 31.0f;
        float oml = 1.0f - lam;
        float fy = yu * lam + yv * oml - 0.5f;
        float fx = xu * lam + xv * oml - 0.5f;
        float y0f = fminf(fmaxf(floorf(fy), 0.0f), 127.0f);
        float x0f = fminf(fmaxf(floorf(fx), 0.0f), 127.0f);
        float y1f = fminf(y0f + 1.0f, 127.0f);
        float x1f = fminf(x0f + 1.0f, 127.0f);
        int y0 = (int)y0f, x0 = (int)x0f, y1 = (int)y1f, x1 = (int)x1f;
        float wy0 = fy - y0f, wy1 = y1f - fy;
        float wx0 = fx - x0f, wx1 = x1f - fx;
        s_o[j][0] = (y0 * HW + x0) * DLOI;
        s_o[j][1] = (y1 * HW + x0) * DLOI;
        s_o[j][2] = (y0 * HW + x1) * DLOI;
        s_o[j][3] = (y1 * HW + x1) * DLOI;
        s_w[j][0] = wy1 * wx1;
        s_w[j][1] = wy0 * wx1;
        s_w[j][2] = wy1 * wx0;
        s_w[j][3] = wy0 * wx0;
    }
    __syncthreads();

    const int cg = t & 31;
    const int jg = t >> 5;
    const float* xfb = g_xf + (size_t)b * NPIX * DLOI + cg * 4;

    float4 gm = make_float4(-INFINITY, -INFINITY, -INFINITY, -INFINITY);
    #pragma unroll
    for (int jj = 0; jj < 8; jj++) {
        int j = jg * 8 + jj;
        int4  o = *(const int4*)s_o[j];
        float4 w = *(const float4*)s_w[j];
        float4 c0 = *(const float4*)(xfb + o.x);
        float4 c1 = *(const float4*)(xfb + o.y);
        float4 c2 = *(const float4*)(xfb + o.z);
        float4 c3 = *(const float4*)(xfb + o.w);
        float4 v;
        v.x = c0.x * w.x + c1.x * w.y + c2.x * w.z + c3.x * w.w;
        v.y = c0.y * w.x + c1.y * w.y + c2.y * w.z + c3.y * w.w;
        v.z = c0.z * w.x + c1.z * w.y + c2.z * w.z + c3.z * w.w;
        v.w = c0.w * w.x + c1.w * w.y + c2.w * w.z + c3.w * w.w;
        gm.x = fmaxf(gm.x, v.x); gm.y = fmaxf(gm.y, v.y);
        gm.z = fmaxf(gm.z, v.z); gm.w = fmaxf(gm.w, v.w);
        if ((jj & 3) == 3) {
            *(float4*)&stage2[(j >> 2) * 132 + cg * 4] = gm;
            gm = make_float4(-INFINITY, -INFINITY, -INFINITY, -INFINITY);
        }
    }
    __syncthreads();

    __nv_bfloat16* oh = g_xv_hi + (size_t)gp * 1024;
    __nv_bfloat16* ol = g_xv_lo + (size_t)gp * 1024;
    #pragma unroll
    for (int i = 0; i < 8; i++) {
        int l = t + i * 128;                       // linear = c*8+g
        float s = stage2[(l & 7) * 132 + (l >> 3)];
        __nv_bfloat16 h = __float2bfloat16(s);
        oh[l] = h;
        ol[l] = __float2bfloat16(s - __bfloat162float(h));
    }
}

// ---------------- K4: transpose+split w1/w2; zero tile counters -------------
__global__ __launch_bounds__(256) void k_wsplit(const float* __restrict__ W1,
                                                const float* __restrict__ W2) {
    __shared__ float tile[32][33];
    const int tx = threadIdx.x & 31;
    const int ty = threadIdx.x >> 5;
    const int kb = blockIdx.y * 32;
    const int nb = blockIdx.x * 32;
    const int z = blockIdx.z;
    const float* W = z ? W2 : W1;
    __nv_bfloat16* hi = z ? g_w2t_hi : g_w1t_hi;
    __nv_bfloat16* lo = z ? g_w2t_lo : g_w1t_lo;

    if (z == 0 && blockIdx.x == 0 && blockIdx.y == 0 && threadIdx.x == 0) {
        g_tilectr[0] = 0;
        g_tilectr[1] = 0;
        g_tilectr[2] = 0;
    }

    #pragma unroll
    for (int j = 0; j < 4; j++) {
        int kl = ty * 4 + j;
        tile[kl][tx] = W[(size_t)(kb + kl) * DFC + nb + tx];
    }
    __syncthreads();
    #pragma unroll
    for (int j = 0; j < 4; j++) {
        int nl = ty * 4 + j;
        float v = tile[tx][nl];
        __nv_bfloat16 h = __float2bfloat16(v);
        size_t o = (size_t)(nb + nl) * DFC + kb + tx;
        hi[o] = h;
        lo[o] = __float2bfloat16(v - __bfloat162float(h));
    }
}

// ---------------- K5: persistent mma.sync bf16-split GEMM -------------------
// CTA tile 128x256, BK=64, 3 stages, 8 warps (2Mx4N), warp tile 64x64.
// 1 CTA/SM. mode 0: bf16 out+bias+relu; mode 1: fused w3 dot; mode 2: fp32 out.
#define SASTRIDE 72
#define NSTG 3
#define STG_A (128 * SASTRIDE)
#define STG_B (256 * SASTRIDE)
#define GEMM_DSMEM (NSTG * (STG_A + STG_B) * 2)   // 165888 bytes
#define GEMM_CTAS 148

__global__ __launch_bounds__(256, 1) void k_gemm(
        const __nv_bfloat16* __restrict__ Ahi,
        const __nv_bfloat16* __restrict__ Alo,
        const __nv_bfloat16* __restrict__ Bhi,
        const __nv_bfloat16* __restrict__ Blo,
        const float* __restrict__ bias,
        __nv_bfloat16* __restrict__ OutHi,
        __nv_bfloat16* __restrict__ OutLo,
        float* __restrict__ OutF,
        const float* __restrict__ w3,
        float* __restrict__ part,
        int mode, int ctri, int kdim, int cpsShift, int nxShift, int ntiles) {
    extern __shared__ __align__(16) __nv_bfloat16 dsm[];
    __nv_bfloat16* sAbase = dsm;
    __nv_bfloat16* sBbase = dsm + NSTG * STG_A;
    __shared__ int s_tile;

    const int t = threadIdx.x;
    const int wid = t >> 5, lane = t & 31;
    const int wm = wid >> 2, wn = wid & 3;        // warp grid 2(M) x 4(N)
    unsigned int* ctr = &g_tilectr[ctri];
    const int nk = 3 << cpsShift;
    const int kcMask = (1 << cpsShift) - 1;
    const int nxMask = (1 << nxShift) - 1;

    const uint32_t sAu = smem_u32(sAbase);
    const uint32_t sBu = smem_u32(sBbase);
    const int aRowSel = wm * 64 + (lane & 15);
    const int aColSel = (lane >> 4) * 8;
    const int bRowSel = wn * 64 + (lane & 7) + ((lane >> 4) << 3);
    const int bColSel = ((lane >> 3) & 1) * 8;
    const int q = lane >> 2;
    const int rr = (lane & 3) * 2;

    for (;;) {
        if (t == 0) s_tile = (int)atomicAdd(ctr, 1u);
        __syncthreads();
        const int tile = s_tile;
        if (tile >= ntiles) break;
        const int bm = (tile >> nxShift) * 128;
        const int bn = (tile & nxMask) * 256;

        float acc[4][8][4];
        #pragma unroll
        for (int i = 0; i < 4; i++)
            #pragma unroll
            for (int j = 0; j < 8; j++)
                #pragma unroll
                for (int qq = 0; qq < 4; qq++) acc[i][j][qq] = 0.0f;

        auto load_stage = [&](int i, int s) {
            const int split = i >> cpsShift;
            const int kc = i & kcMask;
            const __nv_bfloat16* As = (split == 2) ? Alo : Ahi;
            const __nv_bfloat16* Bs = (split == 1) ? Blo : Bhi;
            #pragma unroll
            for (int p = 0; p < 4; p++) {
                int e = t + p * 256;
                int row = e >> 3, cg = (e & 7) * 8;
                cp16(sAu + (uint32_t)(s * STG_A + row * SASTRIDE + cg) * 2,
                     As + (size_t)(bm + row) * kdim + kc * 64 + cg);
            }
            #pragma unroll
            for (int p = 0; p < 8; p++) {
                int e = t + p * 256;
                int row = e >> 3, cg = (e & 7) * 8;
                cp16(sBu + (uint32_t)(s * STG_B + row * SASTRIDE + cg) * 2,
                     Bs + (size_t)(bn + row) * kdim + kc * 64 + cg);
            }
        };

        #pragma unroll
        for (int p = 0; p < NSTG - 1; p++) {
            load_stage(p, p);
            CP_COMMIT();
        }

        int stg = 0;
        for (int i = 0; i < nk; i++) {
            CP_WAIT(NSTG - 2);
            __syncthreads();

            const uint32_t aBase = sAu + (uint32_t)(stg * STG_A) * 2;
            const uint32_t bBase = sBu + (uint32_t)(stg * STG_B) * 2;
            #pragma unroll
            for (int kk = 0; kk < 64; kk += 16) {
                uint32_t afr[4][4];
                #pragma unroll
                for (int mi = 0; mi < 4; mi++)
                    ldm_x4(afr[mi],
                           aBase + (uint32_t)((aRowSel + mi * 16) * SASTRIDE
                                              + kk + aColSel) * 2);
                uint32_t bfr[4][4];
                #pragma unroll
                for (int np = 0; np < 4; np++)
                    ldm_x4(bfr[np],
                           bBase + (uint32_t)((bRowSel + np * 16) * SASTRIDE
                                              + kk + bColSel) * 2);
                #pragma unroll
                for (int mi = 0; mi < 4; mi++)
                    #pragma unroll
                    for (int np = 0; np < 4; np++) {
                        mma16816(acc[mi][np * 2 + 0], afr[mi], &bfr[np][0]);
                        mma16816(acc[mi][np * 2 + 1], afr[mi], &bfr[np][2]);
                    }
            }
            if (i + NSTG - 1 < nk) {
                int s2 = i + NSTG - 1;
                load_stage(s2, s2 % NSTG);
            }
            CP_COMMIT();
            if (++stg == NSTG) stg = 0;
        }
        CP_WAIT(0);
        __syncthreads();

        // ---------------- epilogue ----------------
        if (mode == 0) {
            #pragma unroll
            for (int mi = 0; mi < 4; mi++) {
                #pragma unroll
                for (int ni = 0; ni < 8; ni++) {
                    int col = bn + wn * 64 + ni * 8 + rr;
                    float b0 = bias[col], b1 = bias[col + 1];
                    #pragma unroll
                    for (int h = 0; h < 2; h++) {
                        int row = bm + wm * 64 + mi * 16 + q + h * 8;
                        float v0 = fmaxf(acc[mi][ni][h * 2 + 0] + b0, 0.0f);
                        float v1 = fmaxf(acc[mi][ni][h * 2 + 1] + b1, 0.0f);
                        __nv_bfloat16 h0 = __float2bfloat16(v0);
                        __nv_bfloat16 h1 = __float2bfloat16(v1);
                        __nv_bfloat162 hp; hp.x = h0; hp.y = h1;
                        __nv_bfloat162 lp;
                        lp.x = __float2bfloat16(v0 - __bfloat162float(h0));
                        lp.y = __float2bfloat16(v1 - __bfloat162float(h1));
                        size_t o = (size_t)row * DFC + col;
                        *(__nv_bfloat162*)(OutHi + o) = hp;
                        *(__nv_bfloat162*)(OutLo + o) = lp;
                    }
                }
            }
        } else if (mode == 2) {
            #pragma unroll
            for (int mi = 0; mi < 4; mi++) {
                #pragma unroll
                for (int ni = 0; ni < 8; ni++) {
                    int col = bn + wn * 64 + ni * 8 + rr;
                    if (col < DLOI) {
                        float b0 = bias[col], b1 = bias[col + 1];
                        #pragma unroll
                        for (int h = 0; h < 2; h++) {
                            int row = bm + wm * 64 + mi * 16 + q + h * 8;
                            float2 o2;
                            o2.x = acc[mi][ni][h * 2 + 0] + b0;
                            o2.y = acc[mi][ni][h * 2 + 1] + b1;
                            *(float2*)(OutF + (size_t)row * DLOI + col) = o2;
                        }
                    }
                }
            }
        } else {
            float* ps = (float*)dsm;               // [8][64]
            #pragma unroll
            for (int mi = 0; mi < 4; mi++) {
                float p0 = 0.0f, p1 = 0.0f;
                #pragma unroll
                for (int ni = 0; ni < 8; ni++) {
                    int col = bn + wn * 64 + ni * 8 + rr;
                    float b0 = bias[col], b1 = bias[col + 1];
                    float w0 = w3[col], w1 = w3[col + 1];
                    p0 += fmaxf(acc[mi][ni][0] + b0, 0.0f) * w0
                        + fmaxf(acc[mi][ni][1] + b1, 0.0f) * w1;
                    p1 += fmaxf(acc[mi][ni][2] + b0, 0.0f) * w0
                        + fmaxf(acc[mi][ni][3] + b1, 0.0f) * w1;
                }
                p0 += __shfl_xor_sync(0xffffffffu, p0, 1);
                p0 += __shfl_xor_sync(0xffffffffu, p0, 2);
                p1 += __shfl_xor_sync(0xffffffffu, p1, 1);
                p1 += __shfl_xor_sync(0xffffffffu, p1, 2);
                if ((lane & 3) == 0) {
                    ps[wid * 64 + mi * 16 + q] = p0;
                    ps[wid * 64 + mi * 16 + 8 + q] = p1;
                }
            }
            __syncthreads();
            if (t < 128) {
                int wmr = t >> 6, loc = t & 63;
                float tot = ps[(wmr * 4 + 0) * 64 + loc]
                          + ps[(wmr * 4 + 1) * 64 + loc]
                          + ps[(wmr * 4 + 2) * 64 + loc]
                          + ps[(wmr * 4 + 3) * 64 + loc];
                part[(size_t)(bm + t) * 4 + (tile & nxMask)] = tot;
            }
        }
        __syncthreads();
    }
}

// ---------------- K6: scores + labels + lines (fused) -----------------------
__global__ void k_out(const float* __restrict__ b3, float* __restrict__ out) {
    const int gp = blockIdx.x * 256 + threadIdx.x;
    if (gp >= NROWS) return;
    const float* pp = g_part + (size_t)gp * 4;
    float s = pp[0] + pp[1] + pp[2] + pp[3];
    out[gp] = s + b3[0];
    out[NROWS + gp] = 0.0f;
    const int b = gp / NPAIR;
    const int p = gp - b * NPAIR;
    int u, v;
    pair_uv(p, u, v);
    float* L = out + 2 * NROWS + (size_t)gp * 4;
    L[0] = g_xy[b][u][0];
    L[1] = g_xy[b][u][1];
    L[2] = g_xy[b][v][0];
    L[3] = g_xy[b][v][1];
}

// ---------------- launch -----------------------------------------------------
extern "C" void kernel_launch(void* const* d_in, const int* in_sizes, int n_in,
                              void* d_out, int out_size) {
    const float* inputs   = (const float*)d_in[0];
    const float* features = (const float*)d_in[1];
    const float* fc1_w    = (const float*)d_in[2];
    const float* fc1_b    = (const float*)d_in[3];
    const float* w1       = (const float*)d_in[4];
    const float* b1       = (const float*)d_in[5];
    const float* w2       = (const float*)d_in[6];
    const float* b2       = (const float*)d_in[7];
    const float* w3       = (const float*)d_in[8];
    const float* b3       = (const float*)d_in[9];
    float* out = (float*)d_out;

    void *pxf, *pfth, *pftl, *pfch, *pfcl;
    void *pxvh, *pxvl, *ph1h, *ph1l, *pw1h, *pw1l, *pw2h, *pw2l, *ppart;
    cudaGetSymbolAddress(&pxf, g_xf);
    cudaGetSymbolAddress(&pfth, g_ft_hi);
    cudaGetSymbolAddress(&pftl, g_ft_lo);
    cudaGetSymbolAddress(&pfch, g_fc_hi);
    cudaGetSymbolAddress(&pfcl, g_fc_lo);
    cudaGetSymbolAddress(&pxvh, g_xv_hi);
    cudaGetSymbolAddress(&pxvl, g_xv_lo);
    cudaGetSymbolAddress(&ph1h, g_h1_hi);
    cudaGetSymbolAddress(&ph1l, g_h1_lo);
    cudaGetSymbolAddress(&pw1h, g_w1t_hi);
    cudaGetSymbolAddress(&pw1l, g_w1t_lo);
    cudaGetSymbolAddress(&pw2h, g_w2t_hi);
    cudaGetSymbolAddress(&pw2l, g_w2t_lo);
    cudaGetSymbolAddress(&ppart, g_part);

    const size_t topk_smem = (size_t)(NPIX * 2 + 512) * 4 + 512 * 4 + 64 + 64 + 512;
    cudaFuncSetAttribute(k_topk, cudaFuncAttributeMaxDynamicSharedMemorySize,
                         (int)topk_smem);
    cudaFuncSetAttribute(k_gemm, cudaFuncAttributeMaxDynamicSharedMemorySize,
                         GEMM_DSMEM);

    k_wsplit<<<dim3(32, 32, 2), 256>>>(w1, w2);
    k_ftsplit<<<dim3(NPIX / 32, 8, BATCH), 256>>>(features);
    k_fsplit<<<(256 * 256 + 255) / 256, 256>>>(fc1_w);

    // xf = features^T @ fc1_w^T + fc1_b   (M=32768, N=128 padded to 256, K=256)
    k_gemm<<<GEMM_CTAS, 256, GEMM_DSMEM>>>(
        (const __nv_bfloat16*)pfth, (const __nv_bfloat16*)pftl,
        (const __nv_bfloat16*)pfch, (const __nv_bfloat16*)pfcl,
        fc1_b, nullptr, nullptr, (float*)pxf, nullptr, nullptr,
        2, 0, 256, 2, 0, MPIX / 128);

    k_topk<<<BATCH, 512, topk_smem>>>(inputs);
    k_pool<<<NROWS, 128>>>();

    k_gemm<<<GEMM_CTAS, 256, GEMM_DSMEM>>>(
        (const __nv_bfloat16*)pxvh, (const __nv_bfloat16*)pxvl,
        (const __nv_bfloat16*)pw1h, (const __nv_bfloat16*)pw1l,
        b1, (__nv_bfloat16*)ph1h, (__nv_bfloat16*)ph1l, nullptr,
        nullptr, nullptr, 0, 1, DFC, 4, 2, 4 * (NROWS / 128));
    k_gemm<<<GEMM_CTAS, 256, GEMM_DSMEM>>>(
        (const __nv_bfloat16*)ph1h, (const __nv_bfloat16*)ph1l,
        (const __nv_bfloat16*)pw2h, (const __nv_bfloat16*)pw2l,
        b2, nullptr, nullptr, nullptr,
        w3, (float*)ppart, 1, 2, DFC, 4, 2, 4 * (NROWS / 128));

    k_out<<<(NROWS + 255) / 256, 256>>>(b3, out);
}

// round 13
// speedup vs baseline: 1.0885x; 1.0885x over previous
#include <cuda_runtime.h>
#include <cuda_bf16.h>
#include <math.h>
#include <stdint.h>

#define HW 128
#define NPIX 16384
#define BATCH 2
#define KJ 128
#define NPAIR 8128
#define NROWS (BATCH * NPAIR)   // 16256
#define DLOI 128
#define DFC 1024
#define MPIX (BATCH * NPIX)     // 32768

// ---------------- scratch (device globals; no allocations allowed) ----------
__device__ float g_xf[(size_t)MPIX * DLOI];   // (b*pix, d)
__device__ float g_xy[BATCH][KJ][2];
__device__ __align__(16) __nv_bfloat16 g_ft_hi[(size_t)MPIX * 256];
__device__ __align__(16) __nv_bfloat16 g_ft_lo[(size_t)MPIX * 256];
__device__ __align__(16) __nv_bfloat16 g_fc_hi[DLOI * 256];
__device__ __align__(16) __nv_bfloat16 g_fc_lo[DLOI * 256];
__device__ __align__(16) __nv_bfloat16 g_xv_hi[(size_t)NROWS * DFC];
__device__ __align__(16) __nv_bfloat16 g_xv_lo[(size_t)NROWS * DFC];
__device__ __align__(16) __nv_bfloat16 g_h1_hi[(size_t)NROWS * DFC];
__device__ __align__(16) __nv_bfloat16 g_h1_lo[(size_t)NROWS * DFC];
__device__ __align__(16) __nv_bfloat16 g_w1t_hi[DFC * DFC];
__device__ __align__(16) __nv_bfloat16 g_w1t_lo[DFC * DFC];
__device__ __align__(16) __nv_bfloat16 g_w2t_hi[DFC * DFC];
__device__ __align__(16) __nv_bfloat16 g_w2t_lo[DFC * DFC];
__device__ float g_part[(size_t)NROWS * 8];
__device__ unsigned int g_tilectr[3];

// ---------------- helpers ----------------------------------------------------
__device__ __forceinline__ uint32_t smem_u32(const void* p) {
    uint32_t a;
    asm("{ .reg .u64 t; cvta.to.shared.u64 t, %1; cvt.u32.u64 %0, t; }"
        : "=r"(a) : "l"(p));
    return a;
}
__device__ __forceinline__ void cp16(uint32_t s, const void* g) {
    asm volatile("cp.async.cg.shared.global [%0], [%1], 16;"
                 :: "r"(s), "l"(g) : "memory");
}
#define CP_COMMIT() asm volatile("cp.async.commit_group;" ::: "memory")
#define CP_WAIT(n)  asm volatile("cp.async.wait_group %0;" :: "n"(n) : "memory")

__device__ __forceinline__ void ldm_x4(uint32_t* r, uint32_t addr) {
    asm volatile("ldmatrix.sync.aligned.m8n8.x4.shared.b16 {%0,%1,%2,%3}, [%4];"
                 : "=r"(r[0]), "=r"(r[1]), "=r"(r[2]), "=r"(r[3]) : "r"(addr));
}
__device__ __forceinline__ void mma16816(float* c, const uint32_t* a,
                                         const uint32_t* b) {
    asm volatile(
        "mma.sync.aligned.m16n8k16.row.col.f32.bf16.bf16.f32 "
        "{%0,%1,%2,%3}, {%4,%5,%6,%7}, {%8,%9}, {%0,%1,%2,%3};"
        : "+f"(c[0]), "+f"(c[1]), "+f"(c[2]), "+f"(c[3])
        : "r"(a[0]), "r"(a[1]), "r"(a[2]), "r"(a[3]), "r"(b[0]), "r"(b[1]));
}

// ---------------- pair index helpers (triu_indices(K=128, k=1)) -------------
__device__ __forceinline__ int pair_off(int u) { return u * (255 - u) / 2; }
__device__ __forceinline__ void pair_uv(int p, int& u, int& v) {
    int uu = (int)((255.0 - sqrt(255.0 * 255.0 - 8.0 * (double)p)) * 0.5);
    if (uu < 0) uu = 0;
    if (uu > 126) uu = 126;
    while (uu < 126 && pair_off(uu + 1) <= p) uu++;
    while (uu > 0 && pair_off(uu) > p) uu--;
    u = uu;
    v = uu + 1 + (p - pair_off(uu));
}

// ---------------- K1: jmap + NMS + exact top-128 + junction coords ----------
__global__ void k_topk(const float* __restrict__ inputs) {
    extern __shared__ float sh[];
    float* smap = sh;
    float* nmsv = smap + NPIX;
    float* bv   = nmsv + NPIX;
    int*   bi   = (int*)(bv + 512);
    float* wv   = (float*)(bi + 512);
    int*   wi   = (int*)(wv + 16);
    int*   topidx = wi + 16;

    const int b = blockIdx.x;
    const int t = threadIdx.x;
    const float* in0 = inputs + (size_t)b * 5 * NPIX;
    const float* in1 = in0 + NPIX;

    for (int i = t; i < NPIX; i += 512) {
        float x0 = in0[i], x1 = in1[i];
        float m = fmaxf(x0, x1);
        float e0 = expf(x0 - m), e1 = expf(x1 - m);
        smap[i] = e1 / (e0 + e1);
    }
    __syncthreads();

    float bval = -1.0f;
    int bidx = t * 32;
    for (int j = 0; j < 32; j++) {
        int idx = t * 32 + j;
        int y = idx >> 7, x = idx & 127;
        float v = smap[idx];
        float m = v;
        #pragma unroll
        for (int dy = -1; dy <= 1; dy++) {
            int yy = y + dy;
            if (yy < 0 || yy >= HW) continue;
            #pragma unroll
            for (int dx = -1; dx <= 1; dx++) {
                int xx = x + dx;
                if (xx < 0 || xx >= HW) continue;
                m = fmaxf(m, smap[yy * HW + xx]);
            }
        }
        float nv = (v == m) ? v : 0.0f;
        nmsv[idx] = nv;
        if (nv > bval) { bval = nv; bidx = idx; }
    }
    bv[t] = bval; bi[t] = bidx;
    __syncthreads();

    for (int r = 0; r < KJ; r++) {
        float v = bv[t];
        int ix = bi[t];
        #pragma unroll
        for (int off = 16; off; off >>= 1) {
            float v2 = __shfl_down_sync(0xffffffffu, v, off);
            int   i2 = __shfl_down_sync(0xffffffffu, ix, off);
            if (v2 > v || (v2 == v && i2 < ix)) { v = v2; ix = i2; }
        }
        if ((t & 31) == 0) { wv[t >> 5] = v; wi[t >> 5] = ix; }
        __syncthreads();
        if (t < 32) {
            float v3 = (t < 16) ? wv[t] : -2.0f;
            int   i3 = (t < 16) ? wi[t] : 0x7fffffff;
            #pragma unroll
            for (int off = 8; off; off >>= 1) {
                float v2 = __shfl_down_sync(0xffffffffu, v3, off);
                int   i2 = __shfl_down_sync(0xffffffffu, i3, off);
                if (v2 > v3 || (v2 == v3 && i2 < i3)) { v3 = v2; i3 = i2; }
            }
            if (t == 0) topidx[r] = i3;
        }
        __syncthreads();
        int win = topidx[r];
        if (t == (win >> 5)) {
            nmsv[win] = -1.0f;
            float nb = -1.0f;
            int nbi = t * 32;
            for (int j = 0; j < 32; j++) {
                float nv = nmsv[t * 32 + j];
                if (nv > nb) { nb = nv; nbi = t * 32 + j; }
            }
            bv[t] = nb; bi[t] = nbi;
        }
        __syncthreads();
    }

    if (t < KJ) {
        int idx = topidx[t];
        const float* in3 = in0 + 3 * NPIX;
        const float* in4 = in0 + 4 * NPIX;
        float sy = 1.0f / (1.0f + expf(-in3[idx]));
        float sx = 1.0f / (1.0f + expf(-in4[idx]));
        g_xy[b][t][0] = (float)(idx >> 7) + sy;
        g_xy[b][t][1] = (float)(idx & 127) + sx;
    }
}

// ---------------- K2a: transpose+split features (c,pix)->(pix,c) bf16 -------
__global__ __launch_bounds__(256) void k_ftsplit(const float* __restrict__ F) {
    __shared__ float tile[32][33];
    const int tx = threadIdx.x & 31;
    const int ty = threadIdx.x >> 5;
    const int pixb = blockIdx.x * 32;
    const int cb = blockIdx.y * 32;
    const int b = blockIdx.z;
    const float* src = F + (size_t)b * 256 * NPIX;
    #pragma unroll
    for (int j = 0; j < 4; j++) {
        int cl = ty * 4 + j;
        tile[cl][tx] = src[(size_t)(cb + cl) * NPIX + pixb + tx];
    }
    __syncthreads();
    #pragma unroll
    for (int j = 0; j < 4; j++) {
        int pl = ty * 4 + j;
        float v = tile[tx][pl];
        __nv_bfloat16 h = __float2bfloat16(v);
        size_t o = ((size_t)b * NPIX + pixb + pl) * 256 + cb + tx;
        g_ft_hi[o] = h;
        g_ft_lo[o] = __float2bfloat16(v - __bfloat162float(h));
    }
}

// ---------------- K2b: split fc1_w (already (N=128,K=256) K-contig) ---------
__global__ void k_fsplit(const float* __restrict__ W) {
    int i = blockIdx.x * 256 + threadIdx.x;
    if (i < DLOI * 256) {
        float v = W[i];
        __nv_bfloat16 h = __float2bfloat16(v);
        g_fc_hi[i] = h;
        g_fc_lo[i] = __float2bfloat16(v - __bfloat162float(h));
    }
}

// ---------------- K3: LOI pool (float4 gathers) --> xv bf16 hi/lo -----------
__global__ __launch_bounds__(128) void k_pool() {
    const int gp = blockIdx.x;
    const int b = gp / NPAIR;
    const int p = gp - b * NPAIR;
    const int t = threadIdx.x;

    __shared__ __align__(16) int   s_o[32][4];
    __shared__ __align__(16) float s_w[32][4];
    __shared__ __align__(16) float stage2[8 * 132];

    if (t < 32) {
        int u, v;
        pair_uv(p, u, v);
        const float yu = g_xy[b][u][0], xu = g_xy[b][u][1];
        const float yv = g_xy[b][v][0], xv = g_xy[b][v][1];
        const int j = t;
        float lam = (float)j / 31.0f;
        float oml = 1.0f - lam;
        float fy = yu * lam + yv * oml - 0.5f;
        float fx = xu * lam + xv * oml - 0.5f;
        float y0f = fminf(fmaxf(floorf(fy), 0.0f), 127.0f);
        float x0f = fminf(fmaxf(floorf(fx), 0.0f), 127.0f);
        float y1f = fminf(y0f + 1.0f, 127.0f);
        float x1f = fminf(x0f + 1.0f, 127.0f);
        int y0 = (int)y0f, x0 = (int)x0f, y1 = (int)y1f, x1 = (int)x1f;
        float wy0 = fy - y0f, wy1 = y1f - fy;
        float wx0 = fx - x0f, wx1 = x1f - fx;
        s_o[j][0] = (y0 * HW + x0) * DLOI;
        s_o[j][1] = (y1 * HW + x0) * DLOI;
        s_o[j][2] = (y0 * HW + x1) * DLOI;
        s_o[j][3] = (y1 * HW + x1) * DLOI;
        s_w[j][0] = wy1 * wx1;
        s_w[j][1] = wy0 * wx1;
        s_w[j][2] = wy1 * wx0;
        s_w[j][3] = wy0 * wx0;
    }
    __syncthreads();

    const int cg = t & 31;
    const int jg = t >> 5;
    const float* xfb = g_xf + (size_t)b * NPIX * DLOI + cg * 4;

    float4 gm = make_float4(-INFINITY, -INFINITY, -INFINITY, -INFINITY);
    #pragma unroll
    for (int jj = 0; jj < 8; jj++) {
        int j = jg * 8 + jj;
        int4  o = *(const int4*)s_o[j];
        float4 w = *(const float4*)s_w[j];
        float4 c0 = *(const float4*)(xfb + o.x);
        float4 c1 = *(const float4*)(xfb + o.y);
        float4 c2 = *(const float4*)(xfb + o.z);
        float4 c3 = *(const float4*)(xfb + o.w);
        float4 v;
        v.x = c0.x * w.x + c1.x * w.y + c2.x * w.z + c3.x * w.w;
        v.y = c0.y * w.x + c1.y * w.y + c2.y * w.z + c3.y * w.w;
        v.z = c0.z * w.x + c1.z * w.y + c2.z * w.z + c3.z * w.w;
        v.w = c0.w * w.x + c1.w * w.y + c2.w * w.z + c3.w * w.w;
        gm.x = fmaxf(gm.x, v.x); gm.y = fmaxf(gm.y, v.y);
        gm.z = fmaxf(gm.z, v.z); gm.w = fmaxf(gm.w, v.w);
        if ((jj & 3) == 3) {
            *(float4*)&stage2[(j >> 2) * 132 + cg * 4] = gm;
            gm = make_float4(-INFINITY, -INFINITY, -INFINITY, -INFINITY);
        }
    }
    __syncthreads();

    __nv_bfloat16* oh = g_xv_hi + (size_t)gp * 1024;
    __nv_bfloat16* ol = g_xv_lo + (size_t)gp * 1024;
    #pragma unroll
    for (int i = 0; i < 8; i++) {
        int l = t + i * 128;                       // linear = c*8+g
        float s = stage2[(l & 7) * 132 + (l >> 3)];
        __nv_bfloat16 h = __float2bfloat16(s);
        oh[l] = h;
        ol[l] = __float2bfloat16(s - __bfloat162float(h));
    }
}

// ---------------- K4: transpose+split w1/w2; zero tile counters -------------
__global__ __launch_bounds__(256) void k_wsplit(const float* __restrict__ W1,
                                                const float* __restrict__ W2) {
    __shared__ float tile[32][33];
    const int tx = threadIdx.x & 31;
    const int ty = threadIdx.x >> 5;
    const int kb = blockIdx.y * 32;
    const int nb = blockIdx.x * 32;
    const int z = blockIdx.z;
    const float* W = z ? W2 : W1;
    __nv_bfloat16* hi = z ? g_w2t_hi : g_w1t_hi;
    __nv_bfloat16* lo = z ? g_w2t_lo : g_w1t_lo;

    if (z == 0 && blockIdx.x == 0 && blockIdx.y == 0 && threadIdx.x == 0) {
        g_tilectr[0] = 0;
        g_tilectr[1] = 0;
        g_tilectr[2] = 0;
    }

    #pragma unroll
    for (int j = 0; j < 4; j++) {
        int kl = ty * 4 + j;
        tile[kl][tx] = W[(size_t)(kb + kl) * DFC + nb + tx];
    }
    __syncthreads();
    #pragma unroll
    for (int j = 0; j < 4; j++) {
        int nl = ty * 4 + j;
        float v = tile[tx][nl];
        __nv_bfloat16 h = __float2bfloat16(v);
        size_t o = (size_t)(nb + nl) * DFC + kb + tx;
        hi[o] = h;
        lo[o] = __float2bfloat16(v - __bfloat162float(h));
    }
}

// ---------------- K5: persistent fused-split mma.sync GEMM ------------------
// CTA tile 128x128, BK=32, all 3 split terms per chunk (Ahi/Alo/Bhi/Blo staged
// together). 2 stages, 8 warps (4Mx2N, warp tile 32x64), 2 CTA/SM.
#define SASTRIDE 40                               // 32 + 8 pad (bf16 elems)
#define NSTG 2
#define MAT_ELEMS (128 * SASTRIDE)                // 5120 per matrix
#define STG_ELEMS (4 * MAT_ELEMS)                 // Ahi|Alo|Bhi|Blo
#define GEMM_DSMEM (NSTG * STG_ELEMS * 2)         // 81920 bytes
#define GEMM_CTAS 296

__global__ __launch_bounds__(256, 2) void k_gemm(
        const __nv_bfloat16* __restrict__ Ahi,
        const __nv_bfloat16* __restrict__ Alo,
        const __nv_bfloat16* __restrict__ Bhi,
        const __nv_bfloat16* __restrict__ Blo,
        const float* __restrict__ bias,
        __nv_bfloat16* __restrict__ OutHi,
        __nv_bfloat16* __restrict__ OutLo,
        float* __restrict__ OutF,
        const float* __restrict__ w3,
        float* __restrict__ part,
        int mode, int ctri, int kdim, int nxShift, int ntiles) {
    extern __shared__ __align__(16) __nv_bfloat16 dsm[];
    __shared__ int s_tile;

    const int t = threadIdx.x;
    const int wid = t >> 5, lane = t & 31;
    const int wm = wid >> 1, wn = wid & 1;        // warp grid 4(M) x 2(N)
    unsigned int* ctr = &g_tilectr[ctri];
    const int nk = kdim >> 5;                     // BK=32 chunks
    const int nxMask = (1 << nxShift) - 1;

    const uint32_t smemB = smem_u32(dsm);
    const int aRowSel = wm * 32 + (lane & 15);
    const int aColSel = (lane >> 4) * 8;
    const int bRowSel = wn * 64 + (lane & 7) + ((lane >> 4) << 3);
    const int bColSel = ((lane >> 3) & 1) * 8;
    const int q = lane >> 2;
    const int rr = (lane & 3) * 2;

    // per-thread cp.async slot: 2048 cp16 per stage, 8 per thread
    for (;;) {
        if (t == 0) s_tile = (int)atomicAdd(ctr, 1u);
        __syncthreads();
        const int tile = s_tile;
        if (tile >= ntiles) break;
        const int bm = (tile >> nxShift) * 128;
        const int bn = (tile & nxMask) * 128;

        float acc[2][8][4];
        #pragma unroll
        for (int i = 0; i < 2; i++)
            #pragma unroll
            for (int j = 0; j < 8; j++)
                #pragma unroll
                for (int qq = 0; qq < 4; qq++) acc[i][j][qq] = 0.0f;

        const __nv_bfloat16* mats[4];
        mats[0] = Ahi + (size_t)bm * kdim;
        mats[1] = Alo + (size_t)bm * kdim;
        mats[2] = Bhi + (size_t)bn * kdim;
        mats[3] = Blo + (size_t)bn * kdim;

        auto load_stage = [&](int kc, int s) {
            #pragma unroll
            for (int p = 0; p < 8; p++) {
                int e = t + p * 256;
                int mat = e >> 9;
                int idx = e & 511;
                int row = idx >> 2, c8 = (idx & 3) * 8;
                cp16(smemB + (uint32_t)(s * STG_ELEMS + mat * MAT_ELEMS
                                        + row * SASTRIDE + c8) * 2,
                     mats[mat] + (size_t)row * kdim + kc * 32 + c8);
            }
        };

        load_stage(0, 0);
        CP_COMMIT();

        for (int i = 0; i < nk; i++) {
            CP_WAIT(0);
            __syncthreads();
            const int stg = i & 1;
            if (i + 1 < nk) {
                load_stage(i + 1, stg ^ 1);
            }
            CP_COMMIT();

            const uint32_t base = smemB + (uint32_t)(stg * STG_ELEMS) * 2;
            const uint32_t aHiB = base;
            const uint32_t aLoB = base + MAT_ELEMS * 2;
            const uint32_t bHiB = base + 2 * MAT_ELEMS * 2;
            const uint32_t bLoB = base + 3 * MAT_ELEMS * 2;

            #pragma unroll
            for (int kk = 0; kk < 32; kk += 16) {
                uint32_t aHi[2][4];
                #pragma unroll
                for (int mi = 0; mi < 2; mi++)
                    ldm_x4(aHi[mi],
                           aHiB + (uint32_t)((aRowSel + mi * 16) * SASTRIDE
                                             + kk + aColSel) * 2);
                uint32_t bHi[4][4];
                #pragma unroll
                for (int np = 0; np < 4; np++)
                    ldm_x4(bHi[np],
                           bHiB + (uint32_t)((bRowSel + np * 16) * SASTRIDE
                                             + kk + bColSel) * 2);
                // term 1: Ahi * Bhi
                #pragma unroll
                for (int mi = 0; mi < 2; mi++)
                    #pragma unroll
                    for (int np = 0; np < 4; np++) {
                        mma16816(acc[mi][np * 2 + 0], aHi[mi], &bHi[np][0]);
                        mma16816(acc[mi][np * 2 + 1], aHi[mi], &bHi[np][2]);
                    }
                // term 2: Ahi * Blo (bLo fragments transient)
                {
                    uint32_t bLo[4][4];
                    #pragma unroll
                    for (int np = 0; np < 4; np++)
                        ldm_x4(bLo[np],
                               bLoB + (uint32_t)((bRowSel + np * 16) * SASTRIDE
                                                 + kk + bColSel) * 2);
                    #pragma unroll
                    for (int mi = 0; mi < 2; mi++)
                        #pragma unroll
                        for (int np = 0; np < 4; np++) {
                            mma16816(acc[mi][np * 2 + 0], aHi[mi], &bLo[np][0]);
                            mma16816(acc[mi][np * 2 + 1], aHi[mi], &bLo[np][2]);
                        }
                }
                // term 3: Alo * Bhi (aLo fragments transient)
                {
                    uint32_t aLo[2][4];
                    #pragma unroll
                    for (int mi = 0; mi < 2; mi++)
                        ldm_x4(aLo[mi],
                               aLoB + (uint32_t)((aRowSel + mi * 16) * SASTRIDE
                                                 + kk + aColSel) * 2);
                    #pragma unroll
                    for (int mi = 0; mi < 2; mi++)
                        #pragma unroll
                        for (int np = 0; np < 4; np++) {
                            mma16816(acc[mi][np * 2 + 0], aLo[mi], &bHi[np][0]);
                            mma16816(acc[mi][np * 2 + 1], aLo[mi], &bHi[np][2]);
                        }
                }
            }
        }
        CP_WAIT(0);
        __syncthreads();

        // ---------------- epilogue ----------------
        if (mode == 0) {
            #pragma unroll
            for (int mi = 0; mi < 2; mi++) {
                #pragma unroll
                for (int ni = 0; ni < 8; ni++) {
                    int col = bn + wn * 64 + ni * 8 + rr;
                    float b0 = bias[col], b1 = bias[col + 1];
                    #pragma unroll
                    for (int h = 0; h < 2; h++) {
                        int row = bm + wm * 32 + mi * 16 + q + h * 8;
                        float v0 = fmaxf(acc[mi][ni][h * 2 + 0] + b0, 0.0f);
                        float v1 = fmaxf(acc[mi][ni][h * 2 + 1] + b1, 0.0f);
                        __nv_bfloat16 h0 = __float2bfloat16(v0);
                        __nv_bfloat16 h1 = __float2bfloat16(v1);
                        __nv_bfloat162 hp; hp.x = h0; hp.y = h1;
                        __nv_bfloat162 lp;
                        lp.x = __float2bfloat16(v0 - __bfloat162float(h0));
                        lp.y = __float2bfloat16(v1 - __bfloat162float(h1));
                        size_t o = (size_t)row * DFC + col;
                        *(__nv_bfloat162*)(OutHi + o) = hp;
                        *(__nv_bfloat162*)(OutLo + o) = lp;
                    }
                }
            }
        } else if (mode == 2) {
            #pragma unroll
            for (int mi = 0; mi < 2; mi++) {
                #pragma unroll
                for (int ni = 0; ni < 8; ni++) {
                    int col = bn + wn * 64 + ni * 8 + rr;
                    float b0 = bias[col], b1 = bias[col + 1];
                    #pragma unroll
                    for (int h = 0; h < 2; h++) {
                        int row = bm + wm * 32 + mi * 16 + q + h * 8;
                        float2 o2;
                        o2.x = acc[mi][ni][h * 2 + 0] + b0;
                        o2.y = acc[mi][ni][h * 2 + 1] + b1;
                        *(float2*)(OutF + (size_t)row * DLOI + col) = o2;
                    }
                }
            }
        } else {
            float* ps = (float*)dsm;               // [8][32]
            #pragma unroll
            for (int mi = 0; mi < 2; mi++) {
                float p0 = 0.0f, p1 = 0.0f;
                #pragma unroll
                for (int ni = 0; ni < 8; ni++) {
                    int col = bn + wn * 64 + ni * 8 + rr;
                    float b0 = bias[col], b1 = bias[col + 1];
                    float w0 = w3[col], w1 = w3[col + 1];
                    p0 += fmaxf(acc[mi][ni][0] + b0, 0.0f) * w0
                        + fmaxf(acc[mi][ni][1] + b1, 0.0f) * w1;
                    p1 += fmaxf(acc[mi][ni][2] + b0, 0.0f) * w0
                        + fmaxf(acc[mi][ni][3] + b1, 0.0f) * w1;
                }
                p0 += __shfl_xor_sync(0xffffffffu, p0, 1);
                p0 += __shfl_xor_sync(0xffffffffu, p0, 2);
                p1 += __shfl_xor_sync(0xffffffffu, p1, 1);
                p1 += __shfl_xor_sync(0xffffffffu, p1, 2);
                if ((lane & 3) == 0) {
                    ps[wid * 32 + mi * 16 + q] = p0;
                    ps[wid * 32 + mi * 16 + 8 + q] = p1;
                }
            }
            __syncthreads();
            if (t < 128) {
                int rw = t >> 5, rl = t & 31;
                float tot = ps[(rw * 2 + 0) * 32 + rl]
                          + ps[(rw * 2 + 1) * 32 + rl];
                part[(size_t)(bm + t) * 8 + (tile & nxMask)] = tot;
            }
        }
        __syncthreads();
    }
}

// ---------------- K6: scores + labels + lines (fused) -----------------------
__global__ void k_out(const float* __restrict__ b3, float* __restrict__ out) {
    const int gp = blockIdx.x * 256 + threadIdx.x;
    if (gp >= NROWS) return;
    const float* pp = g_part + (size_t)gp * 8;
    float s = pp[0] + pp[1] + pp[2] + pp[3] + pp[4] + pp[5] + pp[6] + pp[7];
    out[gp] = s + b3[0];
    out[NROWS + gp] = 0.0f;
    const int b = gp / NPAIR;
    const int p = gp - b * NPAIR;
    int u, v;
    pair_uv(p, u, v);
    float* L = out + 2 * NROWS + (size_t)gp * 4;
    L[0] = g_xy[b][u][0];
    L[1] = g_xy[b][u][1];
    L[2] = g_xy[b][v][0];
    L[3] = g_xy[b][v][1];
}

// ---------------- launch -----------------------------------------------------
extern "C" void kernel_launch(void* const* d_in, const int* in_sizes, int n_in,
                              void* d_out, int out_size) {
    const float* inputs   = (const float*)d_in[0];
    const float* features = (const float*)d_in[1];
    const float* fc1_w    = (const float*)d_in[2];
    const float* fc1_b    = (const float*)d_in[3];
    const float* w1       = (const float*)d_in[4];
    const float* b1       = (const float*)d_in[5];
    const float* w2       = (const float*)d_in[6];
    const float* b2       = (const float*)d_in[7];
    const float* w3       = (const float*)d_in[8];
    const float* b3       = (const float*)d_in[9];
    float* out = (float*)d_out;

    void *pxf, *pfth, *pftl, *pfch, *pfcl;
    void *pxvh, *pxvl, *ph1h, *ph1l, *pw1h, *pw1l, *pw2h, *pw2l, *ppart;
    cudaGetSymbolAddress(&pxf, g_xf);
    cudaGetSymbolAddress(&pfth, g_ft_hi);
    cudaGetSymbolAddress(&pftl, g_ft_lo);
    cudaGetSymbolAddress(&pfch, g_fc_hi);
    cudaGetSymbolAddress(&pfcl, g_fc_lo);
    cudaGetSymbolAddress(&pxvh, g_xv_hi);
    cudaGetSymbolAddress(&pxvl, g_xv_lo);
    cudaGetSymbolAddress(&ph1h, g_h1_hi);
    cudaGetSymbolAddress(&ph1l, g_h1_lo);
    cudaGetSymbolAddress(&pw1h, g_w1t_hi);
    cudaGetSymbolAddress(&pw1l, g_w1t_lo);
    cudaGetSymbolAddress(&pw2h, g_w2t_hi);
    cudaGetSymbolAddress(&pw2l, g_w2t_lo);
    cudaGetSymbolAddress(&ppart, g_part);

    const size_t topk_smem = (size_t)(NPIX * 2 + 512) * 4 + 512 * 4 + 64 + 64 + 512;
    cudaFuncSetAttribute(k_topk, cudaFuncAttributeMaxDynamicSharedMemorySize,
                         (int)topk_smem);
    cudaFuncSetAttribute(k_gemm, cudaFuncAttributeMaxDynamicSharedMemorySize,
                         GEMM_DSMEM);

    k_wsplit<<<dim3(32, 32, 2), 256>>>(w1, w2);
    k_ftsplit<<<dim3(NPIX / 32, 8, BATCH), 256>>>(features);
    k_fsplit<<<(DLOI * 256 + 255) / 256, 256>>>(fc1_w);

    // xf = features^T @ fc1_w^T + fc1_b   (M=32768, N=128, K=256), fp32 out
    k_gemm<<<GEMM_CTAS, 256, GEMM_DSMEM>>>(
        (const __nv_bfloat16*)pfth, (const __nv_bfloat16*)pftl,
        (const __nv_bfloat16*)pfch, (const __nv_bfloat16*)pfcl,
        fc1_b, nullptr, nullptr, (float*)pxf, nullptr, nullptr,
        2, 0, 256, 0, MPIX / 128);

    k_topk<<<BATCH, 512, topk_smem>>>(inputs);
    k_pool<<<NROWS, 128>>>();

    k_gemm<<<GEMM_CTAS, 256, GEMM_DSMEM>>>(
        (const __nv_bfloat16*)pxvh, (const __nv_bfloat16*)pxvl,
        (const __nv_bfloat16*)pw1h, (const __nv_bfloat16*)pw1l,
        b1, (__nv_bfloat16*)ph1h, (__nv_bfloat16*)ph1l, nullptr,
        nullptr, nullptr, 0, 1, DFC, 3, 8 * (NROWS / 128));
    k_gemm<<<GEMM_CTAS, 256, GEMM_DSMEM>>>(
        (const __nv_bfloat16*)ph1h, (const __nv_bfloat16*)ph1l,
        (const __nv_bfloat16*)pw2h, (const __nv_bfloat16*)pw2l,
        b2, nullptr, nullptr, nullptr,
        w3, (float*)ppart, 1, 2, DFC, 3, 8 * (NROWS / 128));

    k_out<<<(NROWS + 255) / 256, 256>>>(b3, out);
}

// round 14
// speedup vs baseline: 1.0958x; 1.0067x over previous
#include <cuda_runtime.h>
#include <cuda_bf16.h>
#include <math.h>
#include <stdint.h>

#define HW 128
#define NPIX 16384
#define BATCH 2
#define KJ 128
#define NPAIR 8128
#define NROWS (BATCH * NPAIR)   // 16256
#define DLOI 128
#define DFC 1024
#define MPIX (BATCH * NPIX)     // 32768

// ---------------- scratch (device globals; no allocations allowed) ----------
__device__ float g_xf[(size_t)MPIX * DLOI];   // (b*pix, d)
__device__ float g_xy[BATCH][KJ][2];
__device__ __align__(16) __nv_bfloat16 g_ft_hi[(size_t)MPIX * 256];
__device__ __align__(16) __nv_bfloat16 g_ft_lo[(size_t)MPIX * 256];
__device__ __align__(16) __nv_bfloat16 g_fc_hi[DLOI * 256];
__device__ __align__(16) __nv_bfloat16 g_fc_lo[DLOI * 256];
__device__ __align__(16) __nv_bfloat16 g_xv_hi[(size_t)NROWS * DFC];
__device__ __align__(16) __nv_bfloat16 g_xv_lo[(size_t)NROWS * DFC];
__device__ __align__(16) __nv_bfloat16 g_h1_hi[(size_t)NROWS * DFC];
__device__ __align__(16) __nv_bfloat16 g_h1_lo[(size_t)NROWS * DFC];
__device__ __align__(16) __nv_bfloat16 g_w1t_hi[DFC * DFC];
__device__ __align__(16) __nv_bfloat16 g_w1t_lo[DFC * DFC];
__device__ __align__(16) __nv_bfloat16 g_w2t_hi[DFC * DFC];
__device__ __align__(16) __nv_bfloat16 g_w2t_lo[DFC * DFC];
__device__ float g_part[(size_t)NROWS * 8];
__device__ unsigned int g_tilectr[3];

// ---------------- helpers ----------------------------------------------------
__device__ __forceinline__ uint32_t smem_u32(const void* p) {
    uint32_t a;
    asm("{ .reg .u64 t; cvta.to.shared.u64 t, %1; cvt.u32.u64 %0, t; }"
        : "=r"(a) : "l"(p));
    return a;
}
__device__ __forceinline__ void cp16(uint32_t s, const void* g) {
    asm volatile("cp.async.cg.shared.global [%0], [%1], 16;"
                 :: "r"(s), "l"(g) : "memory");
}
#define CP_COMMIT() asm volatile("cp.async.commit_group;" ::: "memory")
#define CP_WAIT(n)  asm volatile("cp.async.wait_group %0;" :: "n"(n) : "memory")

__device__ __forceinline__ void ldm_x4(uint32_t* r, uint32_t addr) {
    asm volatile("ldmatrix.sync.aligned.m8n8.x4.shared.b16 {%0,%1,%2,%3}, [%4];"
                 : "=r"(r[0]), "=r"(r[1]), "=r"(r[2]), "=r"(r[3]) : "r"(addr));
}
__device__ __forceinline__ void mma16816(float* c, const uint32_t* a,
                                         const uint32_t* b) {
    asm volatile(
        "mma.sync.aligned.m16n8k16.row.col.f32.bf16.bf16.f32 "
        "{%0,%1,%2,%3}, {%4,%5,%6,%7}, {%8,%9}, {%0,%1,%2,%3};"
        : "+f"(c[0]), "+f"(c[1]), "+f"(c[2]), "+f"(c[3])
        : "r"(a[0]), "r"(a[1]), "r"(a[2]), "r"(a[3]), "r"(b[0]), "r"(b[1]));
}

// ---------------- pair index helpers (triu_indices(K=128, k=1)) -------------
__device__ __forceinline__ int pair_off(int u) { return u * (255 - u) / 2; }
__device__ __forceinline__ void pair_uv(int p, int& u, int& v) {
    int uu = (int)((255.0 - sqrt(255.0 * 255.0 - 8.0 * (double)p)) * 0.5);
    if (uu < 0) uu = 0;
    if (uu > 126) uu = 126;
    while (uu < 126 && pair_off(uu + 1) <= p) uu++;
    while (uu > 0 && pair_off(uu) > p) uu--;
    u = uu;
    v = uu + 1 + (p - pair_off(uu));
}

// ---------------- K1: jmap + NMS + exact top-128 + junction coords ----------
__global__ void k_topk(const float* __restrict__ inputs) {
    extern __shared__ float sh[];
    float* smap = sh;
    float* nmsv = smap + NPIX;
    float* bv   = nmsv + NPIX;
    int*   bi   = (int*)(bv + 512);
    float* wv   = (float*)(bi + 512);
    int*   wi   = (int*)(wv + 16);
    int*   topidx = wi + 16;

    const int b = blockIdx.x;
    const int t = threadIdx.x;
    const float* in0 = inputs + (size_t)b * 5 * NPIX;
    const float* in1 = in0 + NPIX;

    for (int i = t; i < NPIX; i += 512) {
        float x0 = in0[i], x1 = in1[i];
        float m = fmaxf(x0, x1);
        float e0 = expf(x0 - m), e1 = expf(x1 - m);
        smap[i] = e1 / (e0 + e1);
    }
    __syncthreads();

    float bval = -1.0f;
    int bidx = t * 32;
    for (int j = 0; j < 32; j++) {
        int idx = t * 32 + j;
        int y = idx >> 7, x = idx & 127;
        float v = smap[idx];
        float m = v;
        #pragma unroll
        for (int dy = -1; dy <= 1; dy++) {
            int yy = y + dy;
            if (yy < 0 || yy >= HW) continue;
            #pragma unroll
            for (int dx = -1; dx <= 1; dx++) {
                int xx = x + dx;
                if (xx < 0 || xx >= HW) continue;
                m = fmaxf(m, smap[yy * HW + xx]);
            }
        }
        float nv = (v == m) ? v : 0.0f;
        nmsv[idx] = nv;
        if (nv > bval) { bval = nv; bidx = idx; }
    }
    bv[t] = bval; bi[t] = bidx;
    __syncthreads();

    for (int r = 0; r < KJ; r++) {
        float v = bv[t];
        int ix = bi[t];
        #pragma unroll
        for (int off = 16; off; off >>= 1) {
            float v2 = __shfl_down_sync(0xffffffffu, v, off);
            int   i2 = __shfl_down_sync(0xffffffffu, ix, off);
            if (v2 > v || (v2 == v && i2 < ix)) { v = v2; ix = i2; }
        }
        if ((t & 31) == 0) { wv[t >> 5] = v; wi[t >> 5] = ix; }
        __syncthreads();
        if (t < 32) {
            float v3 = (t < 16) ? wv[t] : -2.0f;
            int   i3 = (t < 16) ? wi[t] : 0x7fffffff;
            #pragma unroll
            for (int off = 8; off; off >>= 1) {
                float v2 = __shfl_down_sync(0xffffffffu, v3, off);
                int   i2 = __shfl_down_sync(0xffffffffu, i3, off);
                if (v2 > v3 || (v2 == v3 && i2 < i3)) { v3 = v2; i3 = i2; }
            }
            if (t == 0) topidx[r] = i3;
        }
        __syncthreads();
        int win = topidx[r];
        if (t == (win >> 5)) {
            nmsv[win] = -1.0f;
            float nb = -1.0f;
            int nbi = t * 32;
            for (int j = 0; j < 32; j++) {
                float nv = nmsv[t * 32 + j];
                if (nv > nb) { nb = nv; nbi = t * 32 + j; }
            }
            bv[t] = nb; bi[t] = nbi;
        }
        __syncthreads();
    }

    if (t < KJ) {
        int idx = topidx[t];
        const float* in3 = in0 + 3 * NPIX;
        const float* in4 = in0 + 4 * NPIX;
        float sy = 1.0f / (1.0f + expf(-in3[idx]));
        float sx = 1.0f / (1.0f + expf(-in4[idx]));
        g_xy[b][t][0] = (float)(idx >> 7) + sy;
        g_xy[b][t][1] = (float)(idx & 127) + sx;
    }
}

// ---------------- K2a: transpose+split features (c,pix)->(pix,c) bf16 -------
__global__ __launch_bounds__(256) void k_ftsplit(const float* __restrict__ F) {
    __shared__ float tile[32][33];
    const int tx = threadIdx.x & 31;
    const int ty = threadIdx.x >> 5;
    const int pixb = blockIdx.x * 32;
    const int cb = blockIdx.y * 32;
    const int b = blockIdx.z;
    const float* src = F + (size_t)b * 256 * NPIX;
    #pragma unroll
    for (int j = 0; j < 4; j++) {
        int cl = ty * 4 + j;
        tile[cl][tx] = src[(size_t)(cb + cl) * NPIX + pixb + tx];
    }
    __syncthreads();
    #pragma unroll
    for (int j = 0; j < 4; j++) {
        int pl = ty * 4 + j;
        float v = tile[tx][pl];
        __nv_bfloat16 h = __float2bfloat16(v);
        size_t o = ((size_t)b * NPIX + pixb + pl) * 256 + cb + tx;
        g_ft_hi[o] = h;
        g_ft_lo[o] = __float2bfloat16(v - __bfloat162float(h));
    }
}

// ---------------- K2b: split fc1_w (already (N=128,K=256) K-contig) ---------
__global__ void k_fsplit(const float* __restrict__ W) {
    int i = blockIdx.x * 256 + threadIdx.x;
    if (i < DLOI * 256) {
        float v = W[i];
        __nv_bfloat16 h = __float2bfloat16(v);
        g_fc_hi[i] = h;
        g_fc_lo[i] = __float2bfloat16(v - __bfloat162float(h));
    }
}

// ---------------- K3: LOI pool (float4 gathers) --> xv bf16 hi/lo -----------
__global__ __launch_bounds__(128) void k_pool() {
    const int gp = blockIdx.x;
    const int b = gp / NPAIR;
    const int p = gp - b * NPAIR;
    const int t = threadIdx.x;

    __shared__ __align__(16) int   s_o[32][4];
    __shared__ __align__(16) float s_w[32][4];
    __shared__ __align__(16) float stage2[8 * 132];

    if (t < 32) {
        int u, v;
        pair_uv(p, u, v);
        const float yu = g_xy[b][u][0], xu = g_xy[b][u][1];
        const float yv = g_xy[b][v][0], xv = g_xy[b][v][1];
        const int j = t;
        float lam = (float)j / 31.0f;
        float oml = 1.0f - lam;
        float fy = yu * lam + yv * oml - 0.5f;
        float fx = xu * lam + xv * oml - 0.5f;
        float y0f = fminf(fmaxf(floorf(fy), 0.0f), 127.0f);
        float x0f = fminf(fmaxf(floorf(fx), 0.0f), 127.0f);
        float y1f = fminf(y0f + 1.0f, 127.0f);
        float x1f = fminf(x0f + 1.0f, 127.0f);
        int y0 = (int)y0f, x0 = (int)x0f, y1 = (int)y1f, x1 = (int)x1f;
        float wy0 = fy - y0f, wy1 = y1f - fy;
        float wx0 = fx - x0f, wx1 = x1f - fx;
        s_o[j][0] = (y0 * HW + x0) * DLOI;
        s_o[j][1] = (y1 * HW + x0) * DLOI;
        s_o[j][2] = (y0 * HW + x1) * DLOI;
        s_o[j][3] = (y1 * HW + x1) * DLOI;
        s_w[j][0] = wy1 * wx1;
        s_w[j][1] = wy0 * wx1;
        s_w[j][2] = wy1 * wx0;
        s_w[j][3] = wy0 * wx0;
    }
    __syncthreads();

    const int cg = t & 31;
    const int jg = t >> 5;
    const float* xfb = g_xf + (size_t)b * NPIX * DLOI + cg * 4;

    float4 gm = make_float4(-INFINITY, -INFINITY, -INFINITY, -INFINITY);
    #pragma unroll
    for (int jj = 0; jj < 8; jj++) {
        int j = jg * 8 + jj;
        int4  o = *(const int4*)s_o[j];
        float4 w = *(const float4*)s_w[j];
        float4 c0 = *(const float4*)(xfb + o.x);
        float4 c1 = *(const float4*)(xfb + o.y);
        float4 c2 = *(const float4*)(xfb + o.z);
        float4 c3 = *(const float4*)(xfb + o.w);
        float4 v;
        v.x = c0.x * w.x + c1.x * w.y + c2.x * w.z + c3.x * w.w;
        v.y = c0.y * w.x + c1.y * w.y + c2.y * w.z + c3.y * w.w;
        v.z = c0.z * w.x + c1.z * w.y + c2.z * w.z + c3.z * w.w;
        v.w = c0.w * w.x + c1.w * w.y + c2.w * w.z + c3.w * w.w;
        gm.x = fmaxf(gm.x, v.x); gm.y = fmaxf(gm.y, v.y);
        gm.z = fmaxf(gm.z, v.z); gm.w = fmaxf(gm.w, v.w);
        if ((jj & 3) == 3) {
            *(float4*)&stage2[(j >> 2) * 132 + cg * 4] = gm;
            gm = make_float4(-INFINITY, -INFINITY, -INFINITY, -INFINITY);
        }
    }
    __syncthreads();

    __nv_bfloat16* oh = g_xv_hi + (size_t)gp * 1024;
    __nv_bfloat16* ol = g_xv_lo + (size_t)gp * 1024;
    #pragma unroll
    for (int i = 0; i < 8; i++) {
        int l = t + i * 128;                       // linear = c*8+g
        float s = stage2[(l & 7) * 132 + (l >> 3)];
        __nv_bfloat16 h = __float2bfloat16(s);
        oh[l] = h;
        ol[l] = __float2bfloat16(s - __bfloat162float(h));
    }
}

// ---------------- K4: transpose+split w1/w2; zero tile counters -------------
__global__ __launch_bounds__(256) void k_wsplit(const float* __restrict__ W1,
                                                const float* __restrict__ W2) {
    __shared__ float tile[32][33];
    const int tx = threadIdx.x & 31;
    const int ty = threadIdx.x >> 5;
    const int kb = blockIdx.y * 32;
    const int nb = blockIdx.x * 32;
    const int z = blockIdx.z;
    const float* W = z ? W2 : W1;
    __nv_bfloat16* hi = z ? g_w2t_hi : g_w1t_hi;
    __nv_bfloat16* lo = z ? g_w2t_lo : g_w1t_lo;

    if (z == 0 && blockIdx.x == 0 && blockIdx.y == 0 && threadIdx.x == 0) {
        g_tilectr[0] = 0;
        g_tilectr[1] = 0;
        g_tilectr[2] = 0;
    }

    #pragma unroll
    for (int j = 0; j < 4; j++) {
        int kl = ty * 4 + j;
        tile[kl][tx] = W[(size_t)(kb + kl) * DFC + nb + tx];
    }
    __syncthreads();
    #pragma unroll
    for (int j = 0; j < 4; j++) {
        int nl = ty * 4 + j;
        float v = tile[tx][nl];
        __nv_bfloat16 h = __float2bfloat16(v);
        size_t o = (size_t)(nb + nl) * DFC + kb + tx;
        hi[o] = h;
        lo[o] = __float2bfloat16(v - __bfloat162float(h));
    }
}

// ---------------- K5: persistent fused-split mma.sync GEMM ------------------
// CTA tile 128x128, BK=32, all 3 split terms per chunk (Ahi/Alo/Bhi/Blo staged
// together). 2 stages, 8 warps (4Mx2N, warp tile 32x64), 2 CTA/SM.
#define SASTRIDE 40                               // 32 + 8 pad (bf16 elems)
#define NSTG 2
#define MAT_ELEMS (128 * SASTRIDE)                // 5120 per matrix
#define STG_ELEMS (4 * MAT_ELEMS)                 // Ahi|Alo|Bhi|Blo
#define GEMM_DSMEM (NSTG * STG_ELEMS * 2)         // 81920 bytes
#define GEMM_CTAS 296

__global__ __launch_bounds__(256, 2) void k_gemm(
        const __nv_bfloat16* __restrict__ Ahi,
        const __nv_bfloat16* __restrict__ Alo,
        const __nv_bfloat16* __restrict__ Bhi,
        const __nv_bfloat16* __restrict__ Blo,
        const float* __restrict__ bias,
        __nv_bfloat16* __restrict__ OutHi,
        __nv_bfloat16* __restrict__ OutLo,
        float* __restrict__ OutF,
        const float* __restrict__ w3,
        float* __restrict__ part,
        int mode, int ctri, int kdim, int nxShift, int ntiles) {
    extern __shared__ __align__(16) __nv_bfloat16 dsm[];
    __shared__ int s_tile;

    const int t = threadIdx.x;
    const int wid = t >> 5, lane = t & 31;
    const int wm = wid >> 1, wn = wid & 1;        // warp grid 4(M) x 2(N)
    unsigned int* ctr = &g_tilectr[ctri];
    const int nk = kdim >> 5;                     // BK=32 chunks
    const int nxMask = (1 << nxShift) - 1;

    const uint32_t smemB = smem_u32(dsm);
    const int aRowSel = wm * 32 + (lane & 15);
    const int aColSel = (lane >> 4) * 8;
    const int bRowSel = wn * 64 + (lane & 7) + ((lane >> 4) << 3);
    const int bColSel = ((lane >> 3) & 1) * 8;
    const int q = lane >> 2;
    const int rr = (lane & 3) * 2;

    // per-thread cp.async slot: 2048 cp16 per stage, 8 per thread
    for (;;) {
        if (t == 0) s_tile = (int)atomicAdd(ctr, 1u);
        __syncthreads();
        const int tile = s_tile;
        if (tile >= ntiles) break;
        const int bm = (tile >> nxShift) * 128;
        const int bn = (tile & nxMask) * 128;

        float acc[2][8][4];
        #pragma unroll
        for (int i = 0; i < 2; i++)
            #pragma unroll
            for (int j = 0; j < 8; j++)
                #pragma unroll
                for (int qq = 0; qq < 4; qq++) acc[i][j][qq] = 0.0f;

        const __nv_bfloat16* mats[4];
        mats[0] = Ahi + (size_t)bm * kdim;
        mats[1] = Alo + (size_t)bm * kdim;
        mats[2] = Bhi + (size_t)bn * kdim;
        mats[3] = Blo + (size_t)bn * kdim;

        auto load_stage = [&](int kc, int s) {
            #pragma unroll
            for (int p = 0; p < 8; p++) {
                int e = t + p * 256;
                int mat = e >> 9;
                int idx = e & 511;
                int row = idx >> 2, c8 = (idx & 3) * 8;
                cp16(smemB + (uint32_t)(s * STG_ELEMS + mat * MAT_ELEMS
                                        + row * SASTRIDE + c8) * 2,
                     mats[mat] + (size_t)row * kdim + kc * 32 + c8);
            }
        };

        load_stage(0, 0);
        CP_COMMIT();

        for (int i = 0; i < nk; i++) {
            CP_WAIT(0);
            __syncthreads();
            const int stg = i & 1;
            if (i + 1 < nk) {
                load_stage(i + 1, stg ^ 1);
            }
            CP_COMMIT();

            const uint32_t base = smemB + (uint32_t)(stg * STG_ELEMS) * 2;
            const uint32_t aHiB = base;
            const uint32_t aLoB = base + MAT_ELEMS * 2;
            const uint32_t bHiB = base + 2 * MAT_ELEMS * 2;
            const uint32_t bLoB = base + 3 * MAT_ELEMS * 2;

            #pragma unroll
            for (int kk = 0; kk < 32; kk += 16) {
                uint32_t aHi[2][4];
                #pragma unroll
                for (int mi = 0; mi < 2; mi++)
                    ldm_x4(aHi[mi],
                           aHiB + (uint32_t)((aRowSel + mi * 16) * SASTRIDE
                                             + kk + aColSel) * 2);
                uint32_t bHi[4][4];
                #pragma unroll
                for (int np = 0; np < 4; np++)
                    ldm_x4(bHi[np],
                           bHiB + (uint32_t)((bRowSel + np * 16) * SASTRIDE
                                             + kk + bColSel) * 2);
                // term 1: Ahi * Bhi
                #pragma unroll
                for (int mi = 0; mi < 2; mi++)
                    #pragma unroll
                    for (int np = 0; np < 4; np++) {
                        mma16816(acc[mi][np * 2 + 0], aHi[mi], &bHi[np][0]);
                        mma16816(acc[mi][np * 2 + 1], aHi[mi], &bHi[np][2]);
                    }
                // term 2: Ahi * Blo (bLo fragments transient)
                {
                    uint32_t bLo[4][4];
                    #pragma unroll
                    for (int np = 0; np < 4; np++)
                        ldm_x4(bLo[np],
                               bLoB + (uint32_t)((bRowSel + np * 16) * SASTRIDE
                                                 + kk + bColSel) * 2);
                    #pragma unroll
                    for (int mi = 0; mi < 2; mi++)
                        #pragma unroll
                        for (int np = 0; np < 4; np++) {
                            mma16816(acc[mi][np * 2 + 0], aHi[mi], &bLo[np][0]);
                            mma16816(acc[mi][np * 2 + 1], aHi[mi], &bLo[np][2]);
                        }
                }
                // term 3: Alo * Bhi (aLo fragments transient)
                {
                    uint32_t aLo[2][4];
                    #pragma unroll
                    for (int mi = 0; mi < 2; mi++)
                        ldm_x4(aLo[mi],
                               aLoB + (uint32_t)((aRowSel + mi * 16) * SASTRIDE
                                                 + kk + aColSel) * 2);
                    #pragma unroll
                    for (int mi = 0; mi < 2; mi++)
                        #pragma unroll
                        for (int np = 0; np < 4; np++) {
                            mma16816(acc[mi][np * 2 + 0], aLo[mi], &bHi[np][0]);
                            mma16816(acc[mi][np * 2 + 1], aLo[mi], &bHi[np][2]);
                        }
                }
            }
        }
        CP_WAIT(0);
        __syncthreads();

        // ---------------- epilogue ----------------
        if (mode == 0) {
            #pragma unroll
            for (int mi = 0; mi < 2; mi++) {
                #pragma unroll
                for (int ni = 0; ni < 8; ni++) {
                    int col = bn + wn * 64 + ni * 8 + rr;
                    float b0 = bias[col], b1 = bias[col + 1];
                    #pragma unroll
                    for (int h = 0; h < 2; h++) {
                        int row = bm + wm * 32 + mi * 16 + q + h * 8;
                        float v0 = fmaxf(acc[mi][ni][h * 2 + 0] + b0, 0.0f);
                        float v1 = fmaxf(acc[mi][ni][h * 2 + 1] + b1, 0.0f);
                        __nv_bfloat16 h0 = __float2bfloat16(v0);
                        __nv_bfloat16 h1 = __float2bfloat16(v1);
                        __nv_bfloat162 hp; hp.x = h0; hp.y = h1;
                        __nv_bfloat162 lp;
                        lp.x = __float2bfloat16(v0 - __bfloat162float(h0));
                        lp.y = __float2bfloat16(v1 - __bfloat162float(h1));
                        size_t o = (size_t)row * DFC + col;
                        *(__nv_bfloat162*)(OutHi + o) = hp;
                        *(__nv_bfloat162*)(OutLo + o) = lp;
                    }
                }
            }
        } else if (mode == 2) {
            #pragma unroll
            for (int mi = 0; mi < 2; mi++) {
                #pragma unroll
                for (int ni = 0; ni < 8; ni++) {
                    int col = bn + wn * 64 + ni * 8 + rr;
                    float b0 = bias[col], b1 = bias[col + 1];
                    #pragma unroll
                    for (int h = 0; h < 2; h++) {
                        int row = bm + wm * 32 + mi * 16 + q + h * 8;
                        float2 o2;
                        o2.x = acc[mi][ni][h * 2 + 0] + b0;
                        o2.y = acc[mi][ni][h * 2 + 1] + b1;
                        *(float2*)(OutF + (size_t)row * DLOI + col) = o2;
                    }
                }
            }
        } else {
            float* ps = (float*)dsm;               // [8][32]
            #pragma unroll
            for (int mi = 0; mi < 2; mi++) {
                float p0 = 0.0f, p1 = 0.0f;
                #pragma unroll
                for (int ni = 0; ni < 8; ni++) {
                    int col = bn + wn * 64 + ni * 8 + rr;
                    float b0 = bias[col], b1 = bias[col + 1];
                    float w0 = w3[col], w1 = w3[col + 1];
                    p0 += fmaxf(acc[mi][ni][0] + b0, 0.0f) * w0
                        + fmaxf(acc[mi][ni][1] + b1, 0.0f) * w1;
                    p1 += fmaxf(acc[mi][ni][2] + b0, 0.0f) * w0
                        + fmaxf(acc[mi][ni][3] + b1, 0.0f) * w1;
                }
                p0 += __shfl_xor_sync(0xffffffffu, p0, 1);
                p0 += __shfl_xor_sync(0xffffffffu, p0, 2);
                p1 += __shfl_xor_sync(0xffffffffu, p1, 1);
                p1 += __shfl_xor_sync(0xffffffffu, p1, 2);
                if ((lane & 3) == 0) {
                    ps[wid * 32 + mi * 16 + q] = p0;
                    ps[wid * 32 + mi * 16 + 8 + q] = p1;
                }
            }
            __syncthreads();
            if (t < 128) {
                int rw = t >> 5, rl = t & 31;
                float tot = ps[(rw * 2 + 0) * 32 + rl]
                          + ps[(rw * 2 + 1) * 32 + rl];
                part[(size_t)(bm + t) * 8 + (tile & nxMask)] = tot;
            }
        }
        __syncthreads();
    }
}

// ---------------- K6: scores + labels + lines (fused) -----------------------
__global__ void k_out(const float* __restrict__ b3, float* __restrict__ out) {
    const int gp = blockIdx.x * 256 + threadIdx.x;
    if (gp >= NROWS) return;
    const float* pp = g_part + (size_t)gp * 8;
    float s = pp[0] + pp[1] + pp[2] + pp[3] + pp[4] + pp[5] + pp[6] + pp[7];
    out[gp] = s + b3[0];
    out[NROWS + gp] = 0.0f;
    const int b = gp / NPAIR;
    const int p = gp - b * NPAIR;
    int u, v;
    pair_uv(p, u, v);
    float* L = out + 2 * NROWS + (size_t)gp * 4;
    L[0] = g_xy[b][u][0];
    L[1] = g_xy[b][u][1];
    L[2] = g_xy[b][v][0];
    L[3] = g_xy[b][v][1];
}

// ---------------- launch -----------------------------------------------------
extern "C" void kernel_launch(void* const* d_in, const int* in_sizes, int n_in,
                              void* d_out, int out_size) {
    const float* inputs   = (const float*)d_in[0];
    const float* features = (const float*)d_in[1];
    const float* fc1_w    = (const float*)d_in[2];
    const float* fc1_b    = (const float*)d_in[3];
    const float* w1       = (const float*)d_in[4];
    const float* b1       = (const float*)d_in[5];
    const float* w2       = (const float*)d_in[6];
    const float* b2       = (const float*)d_in[7];
    const float* w3       = (const float*)d_in[8];
    const float* b3       = (const float*)d_in[9];
    float* out = (float*)d_out;

    void *pxf, *pfth, *pftl, *pfch, *pfcl;
    void *pxvh, *pxvl, *ph1h, *ph1l, *pw1h, *pw1l, *pw2h, *pw2l, *ppart;
    cudaGetSymbolAddress(&pxf, g_xf);
    cudaGetSymbolAddress(&pfth, g_ft_hi);
    cudaGetSymbolAddress(&pftl, g_ft_lo);
    cudaGetSymbolAddress(&pfch, g_fc_hi);
    cudaGetSymbolAddress(&pfcl, g_fc_lo);
    cudaGetSymbolAddress(&pxvh, g_xv_hi);
    cudaGetSymbolAddress(&pxvl, g_xv_lo);
    cudaGetSymbolAddress(&ph1h, g_h1_hi);
    cudaGetSymbolAddress(&ph1l, g_h1_lo);
    cudaGetSymbolAddress(&pw1h, g_w1t_hi);
    cudaGetSymbolAddress(&pw1l, g_w1t_lo);
    cudaGetSymbolAddress(&pw2h, g_w2t_hi);
    cudaGetSymbolAddress(&pw2l, g_w2t_lo);
    cudaGetSymbolAddress(&ppart, g_part);

    const size_t topk_smem = (size_t)(NPIX * 2 + 512) * 4 + 512 * 4 + 64 + 64 + 512;
    cudaFuncSetAttribute(k_topk, cudaFuncAttributeMaxDynamicSharedMemorySize,
                         (int)topk_smem);
    cudaFuncSetAttribute(k_gemm, cudaFuncAttributeMaxDynamicSharedMemorySize,
                         GEMM_DSMEM);

    k_wsplit<<<dim3(32, 32, 2), 256>>>(w1, w2);
    k_ftsplit<<<dim3(NPIX / 32, 8, BATCH), 256>>>(features);
    k_fsplit<<<(DLOI * 256 + 255) / 256, 256>>>(fc1_w);

    // xf = features^T @ fc1_w^T + fc1_b   (M=32768, N=128, K=256), fp32 out
    k_gemm<<<GEMM_CTAS, 256, GEMM_DSMEM>>>(
        (const __nv_bfloat16*)pfth, (const __nv_bfloat16*)pftl,
        (const __nv_bfloat16*)pfch, (const __nv_bfloat16*)pfcl,
        fc1_b, nullptr, nullptr, (float*)pxf, nullptr, nullptr,
        2, 0, 256, 0, MPIX / 128);

    k_topk<<<BATCH, 512, topk_smem>>>(inputs);
    k_pool<<<NROWS, 128>>>();

    k_gemm<<<GEMM_CTAS, 256, GEMM_DSMEM>>>(
        (const __nv_bfloat16*)pxvh, (const __nv_bfloat16*)pxvl,
        (const __nv_bfloat16*)pw1h, (const __nv_bfloat16*)pw1l,
        b1, (__nv_bfloat16*)ph1h, (__nv_bfloat16*)ph1l, nullptr,
        nullptr, nullptr, 0, 1, DFC, 3, 8 * (NROWS / 128));
    k_gemm<<<GEMM_CTAS, 256, GEMM_DSMEM>>>(
        (const __nv_bfloat16*)ph1h, (const __nv_bfloat16*)ph1l,
        (const __nv_bfloat16*)pw2h, (const __nv_bfloat16*)pw2l,
        b2, nullptr, nullptr, nullptr,
        w3, (float*)ppart, 1, 2, DFC, 3, 8 * (NROWS / 128));

    k_out<<<(NROWS + 255) / 256, 256>>>(b3, out);
}

// round 15
// speedup vs baseline: 1.1937x; 1.0893x over previous
#include <cuda_runtime.h>
#include <cuda_bf16.h>
#include <math.h>
#include <stdint.h>

#define HW 128
#define NPIX 16384
#define BATCH 2
#define KJ 128
#define NPAIR 8128
#define NROWS (BATCH * NPAIR)   // 16256
#define DLOI 128
#define DFC 1024
#define MPIX (BATCH * NPIX)     // 32768

// ---------------- scratch (device globals; no allocations allowed) ----------
__device__ float g_xf[(size_t)MPIX * DLOI];   // (b*pix, d)
__device__ float g_xy[BATCH][KJ][2];
__device__ __align__(16) __nv_bfloat16 g_ft_hi[(size_t)MPIX * 256];
__device__ __align__(16) __nv_bfloat16 g_ft_lo[(size_t)MPIX * 256];
__device__ __align__(16) __nv_bfloat16 g_fc_hi[DLOI * 256];
__device__ __align__(16) __nv_bfloat16 g_fc_lo[DLOI * 256];
__device__ __align__(16) __nv_bfloat16 g_xv_hi[(size_t)NROWS * DFC];
__device__ __align__(16) __nv_bfloat16 g_xv_lo[(size_t)NROWS * DFC];
__device__ __align__(16) __nv_bfloat16 g_h1_hi[(size_t)NROWS * DFC];
__device__ __align__(16) __nv_bfloat16 g_h1_lo[(size_t)NROWS * DFC];
__device__ __align__(16) __nv_bfloat16 g_w1t_hi[DFC * DFC];
__device__ __align__(16) __nv_bfloat16 g_w1t_lo[DFC * DFC];
__device__ __align__(16) __nv_bfloat16 g_w2t_hi[DFC * DFC];
__device__ __align__(16) __nv_bfloat16 g_w2t_lo[DFC * DFC];
__device__ float g_part[(size_t)NROWS * 8];
__device__ unsigned int g_tilectr[3];

// ---------------- helpers ----------------------------------------------------
__device__ __forceinline__ uint32_t smem_u32(const void* p) {
    uint32_t a;
    asm("{ .reg .u64 t; cvta.to.shared.u64 t, %1; cvt.u32.u64 %0, t; }"
        : "=r"(a) : "l"(p));
    return a;
}
__device__ __forceinline__ void cp16(uint32_t s, const void* g) {
    asm volatile("cp.async.cg.shared.global [%0], [%1], 16;"
                 :: "r"(s), "l"(g) : "memory");
}
#define CP_COMMIT() asm volatile("cp.async.commit_group;" ::: "memory")
#define CP_WAIT(n)  asm volatile("cp.async.wait_group %0;" :: "n"(n) : "memory")

__device__ __forceinline__ void ldm_x4(uint32_t* r, uint32_t addr) {
    asm volatile("ldmatrix.sync.aligned.m8n8.x4.shared.b16 {%0,%1,%2,%3}, [%4];"
                 : "=r"(r[0]), "=r"(r[1]), "=r"(r[2]), "=r"(r[3]) : "r"(addr));
}
__device__ __forceinline__ void mma16816(float* c, const uint32_t* a,
                                         const uint32_t* b) {
    asm volatile(
        "mma.sync.aligned.m16n8k16.row.col.f32.bf16.bf16.f32 "
        "{%0,%1,%2,%3}, {%4,%5,%6,%7}, {%8,%9}, {%0,%1,%2,%3};"
        : "+f"(c[0]), "+f"(c[1]), "+f"(c[2]), "+f"(c[3])
        : "r"(a[0]), "r"(a[1]), "r"(a[2]), "r"(a[3]), "r"(b[0]), "r"(b[1]));
}

// ---------------- pair index helpers (triu_indices(K=128, k=1)) -------------
__device__ __forceinline__ int pair_off(int u) { return u * (255 - u) / 2; }
__device__ __forceinline__ void pair_uv(int p, int& u, int& v) {
    int uu = (int)((255.0 - sqrt(255.0 * 255.0 - 8.0 * (double)p)) * 0.5);
    if (uu < 0) uu = 0;
    if (uu > 126) uu = 126;
    while (uu < 126 && pair_off(uu + 1) <= p) uu++;
    while (uu > 0 && pair_off(uu) > p) uu--;
    u = uu;
    v = uu + 1 + (p - pair_off(uu));
}

// ---------------- K1: jmap + NMS + radix-select top-128 ---------------------
// Exact top_k semantics: value desc, index asc tie-break (bits of floats >= 0
// order identically to values; key = ~((bits<<32)|(NPIX-1-idx)) asc-sorted).
__global__ void k_topk(const float* __restrict__ inputs) {
    extern __shared__ float sh[];
    float* smap = sh;                                      // NPIX
    float* nmsv = smap + NPIX;                             // NPIX
    unsigned long long* keys = (unsigned long long*)(nmsv + NPIX);  // 512
    unsigned int* hist = (unsigned int*)(keys + 512);      // 256
    unsigned int* ctrl = hist + 256;                       // 4

    const int b = blockIdx.x;
    const int t = threadIdx.x;
    const float* in0 = inputs + (size_t)b * 5 * NPIX;
    const float* in1 = in0 + NPIX;

    for (int i = t; i < NPIX; i += 512) {
        float x0 = in0[i], x1 = in1[i];
        float m = fmaxf(x0, x1);
        float e0 = expf(x0 - m), e1 = expf(x1 - m);
        smap[i] = e1 / (e0 + e1);
    }
    if (t == 0) { ctrl[0] = 0; ctrl[1] = KJ; ctrl[2] = 0; }
    __syncthreads();

    for (int jj = 0; jj < 32; jj++) {
        int idx = t * 32 + jj;
        int y = idx >> 7, x = idx & 127;
        float v = smap[idx];
        float m = v;
        #pragma unroll
        for (int dy = -1; dy <= 1; dy++) {
            int yy = y + dy;
            if (yy < 0 || yy >= HW) continue;
            #pragma unroll
            for (int dx = -1; dx <= 1; dx++) {
                int xx = x + dx;
                if (xx < 0 || xx >= HW) continue;
                m = fmaxf(m, smap[yy * HW + xx]);
            }
        }
        nmsv[idx] = (v == m) ? v : 0.0f;
    }
    __syncthreads();

    // 4-pass radix: find exact 128th-largest bit pattern T
    #pragma unroll
    for (int pass = 0; pass < 4; pass++) {
        const int shift = 24 - 8 * pass;
        if (t < 256) hist[t] = 0;
        __syncthreads();
        unsigned int prefix = ctrl[0];
        unsigned int himask = (pass == 0) ? 0u : (0xFFFFFFFFu << (shift + 8));
        for (int i = t; i < NPIX; i += 512) {
            unsigned int bits = __float_as_uint(nmsv[i]);
            if ((bits & himask) == prefix)
                atomicAdd(&hist[(bits >> shift) & 0xFF], 1u);
        }
        __syncthreads();
        if (t == 0) {
            unsigned int need = ctrl[1];
            int bsel = 0;
            for (int bb = 255; bb >= 0; bb--) {
                unsigned int c = hist[bb];
                if (c < need) need -= c;
                else { bsel = bb; break; }
            }
            ctrl[0] = prefix | ((unsigned int)bsel << shift);
            ctrl[1] = need;
        }
        __syncthreads();
    }

    const unsigned int T = ctrl[0];
    for (int i = t; i < NPIX; i += 512) {
        unsigned int bits = __float_as_uint(nmsv[i]);
        if (bits >= T) {
            unsigned int slot = atomicAdd(&ctrl[2], 1u);
            if (slot < 512)
                keys[slot] = ~(((unsigned long long)bits << 32)
                               | (unsigned long long)(unsigned int)(NPIX - 1 - i));
        }
    }
    __syncthreads();
    const unsigned int m = ctrl[2] > 512u ? 512u : ctrl[2];
    if ((unsigned int)t >= m) keys[t] = ~0ULL;   // pad sorts last
    __syncthreads();

    // bitonic ascending sort of 512 inverted keys (thread t owns slot t)
    for (int k = 2; k <= 512; k <<= 1) {
        for (int j = k >> 1; j > 0; j >>= 1) {
            int ixj = t ^ j;
            if (ixj > t) {
                bool asc = ((t & k) == 0);
                unsigned long long a = keys[t], c = keys[ixj];
                if ((a > c) == asc) { keys[t] = c; keys[ixj] = a; }
            }
            __syncthreads();
        }
    }

    if (t < KJ) {
        unsigned long long key = ~keys[t];
        int idx = NPIX - 1 - (int)(unsigned int)(key & 0xFFFFFFFFu);
        const float* in3 = in0 + 3 * NPIX;
        const float* in4 = in0 + 4 * NPIX;
        float sy = 1.0f / (1.0f + expf(-in3[idx]));
        float sx = 1.0f / (1.0f + expf(-in4[idx]));
        g_xy[b][t][0] = (float)(idx >> 7) + sy;
        g_xy[b][t][1] = (float)(idx & 127) + sx;
    }
}

// ---------------- K2a: transpose+split features (c,pix)->(pix,c) bf16 -------
__global__ __launch_bounds__(256) void k_ftsplit(const float* __restrict__ F) {
    __shared__ float tile[32][33];
    const int tx = threadIdx.x & 31;
    const int ty = threadIdx.x >> 5;
    const int pixb = blockIdx.x * 32;
    const int cb = blockIdx.y * 32;
    const int b = blockIdx.z;
    const float* src = F + (size_t)b * 256 * NPIX;
    #pragma unroll
    for (int j = 0; j < 4; j++) {
        int cl = ty * 4 + j;
        tile[cl][tx] = src[(size_t)(cb + cl) * NPIX + pixb + tx];
    }
    __syncthreads();
    #pragma unroll
    for (int j = 0; j < 4; j++) {
        int pl = ty * 4 + j;
        float v = tile[tx][pl];
        __nv_bfloat16 h = __float2bfloat16(v);
        size_t o = ((size_t)b * NPIX + pixb + pl) * 256 + cb + tx;
        g_ft_hi[o] = h;
        g_ft_lo[o] = __float2bfloat16(v - __bfloat162float(h));
    }
}

// ---------------- K2b: split fc1_w (already (N=128,K=256) K-contig) ---------
__global__ void k_fsplit(const float* __restrict__ W) {
    int i = blockIdx.x * 256 + threadIdx.x;
    if (i < DLOI * 256) {
        float v = W[i];
        __nv_bfloat16 h = __float2bfloat16(v);
        g_fc_hi[i] = h;
        g_fc_lo[i] = __float2bfloat16(v - __bfloat162float(h));
    }
}

// ---------------- K3: LOI pool (float4 gathers) --> xv bf16 hi/lo -----------
__global__ __launch_bounds__(128) void k_pool() {
    const int gp = blockIdx.x;
    const int b = gp / NPAIR;
    const int p = gp - b * NPAIR;
    const int t = threadIdx.x;

    __shared__ __align__(16) int   s_o[32][4];
    __shared__ __align__(16) float s_w[32][4];
    __shared__ __align__(16) float stage2[8 * 132];

    if (t < 32) {
        int u, v;
        pair_uv(p, u, v);
        const float yu = g_xy[b][u][0], xu = g_xy[b][u][1];
        const float yv = g_xy[b][v][0], xv = g_xy[b][v][1];
        const int j = t;
        float lam = (float)j / 31.0f;
        float oml = 1.0f - lam;
        float fy = yu * lam + yv * oml - 0.5f;
        float fx = xu * lam + xv * oml - 0.5f;
        float y0f = fminf(fmaxf(floorf(fy), 0.0f), 127.0f);
        float x0f = fminf(fmaxf(floorf(fx), 0.0f), 127.0f);
        float y1f = fminf(y0f + 1.0f, 127.0f);
        float x1f = fminf(x0f + 1.0f, 127.0f);
        int y0 = (int)y0f, x0 = (int)x0f, y1 = (int)y1f, x1 = (int)x1f;
        float wy0 = fy - y0f, wy1 = y1f - fy;
        float wx0 = fx - x0f, wx1 = x1f - fx;
        s_o[j][0] = (y0 * HW + x0) * DLOI;
        s_o[j][1] = (y1 * HW + x0) * DLOI;
        s_o[j][2] = (y0 * HW + x1) * DLOI;
        s_o[j][3] = (y1 * HW + x1) * DLOI;
        s_w[j][0] = wy1 * wx1;
        s_w[j][1] = wy0 * wx1;
        s_w[j][2] = wy1 * wx0;
        s_w[j][3] = wy0 * wx0;
    }
    __syncthreads();

    const int cg = t & 31;
    const int jg = t >> 5;
    const float* xfb = g_xf + (size_t)b * NPIX * DLOI + cg * 4;

    float4 gm = make_float4(-INFINITY, -INFINITY, -INFINITY, -INFINITY);
    #pragma unroll
    for (int jj = 0; jj < 8; jj++) {
        int j = jg * 8 + jj;
        int4  o = *(const int4*)s_o[j];
        float4 w = *(const float4*)s_w[j];
        float4 c0 = *(const float4*)(xfb + o.x);
        float4 c1 = *(const float4*)(xfb + o.y);
        float4 c2 = *(const float4*)(xfb + o.z);
        float4 c3 = *(const float4*)(xfb + o.w);
        float4 v;
        v.x = c0.x * w.x + c1.x * w.y + c2.x * w.z + c3.x * w.w;
        v.y = c0.y * w.x + c1.y * w.y + c2.y * w.z + c3.y * w.w;
        v.z = c0.z * w.x + c1.z * w.y + c2.z * w.z + c3.z * w.w;
        v.w = c0.w * w.x + c1.w * w.y + c2.w * w.z + c3.w * w.w;
        gm.x = fmaxf(gm.x, v.x); gm.y = fmaxf(gm.y, v.y);
        gm.z = fmaxf(gm.z, v.z); gm.w = fmaxf(gm.w, v.w);
        if ((jj & 3) == 3) {
            *(float4*)&stage2[(j >> 2) * 132 + cg * 4] = gm;
            gm = make_float4(-INFINITY, -INFINITY, -INFINITY, -INFINITY);
        }
    }
    __syncthreads();

    __nv_bfloat16* oh = g_xv_hi + (size_t)gp * 1024;
    __nv_bfloat16* ol = g_xv_lo + (size_t)gp * 1024;
    #pragma unroll
    for (int i = 0; i < 8; i++) {
        int l = t + i * 128;                       // linear = c*8+g
        float s = stage2[(l & 7) * 132 + (l >> 3)];
        __nv_bfloat16 h = __float2bfloat16(s);
        oh[l] = h;
        ol[l] = __float2bfloat16(s - __bfloat162float(h));
    }
}

// ---------------- K4: transpose+split w1/w2; zero tile counters -------------
__global__ __launch_bounds__(256) void k_wsplit(const float* __restrict__ W1,
                                                const float* __restrict__ W2) {
    __shared__ float tile[32][33];
    const int tx = threadIdx.x & 31;
    const int ty = threadIdx.x >> 5;
    const int kb = blockIdx.y * 32;
    const int nb = blockIdx.x * 32;
    const int z = blockIdx.z;
    const float* W = z ? W2 : W1;
    __nv_bfloat16* hi = z ? g_w2t_hi : g_w1t_hi;
    __nv_bfloat16* lo = z ? g_w2t_lo : g_w1t_lo;

    if (z == 0 && blockIdx.x == 0 && blockIdx.y == 0 && threadIdx.x == 0) {
        g_tilectr[0] = 0;
        g_tilectr[1] = 0;
        g_tilectr[2] = 0;
    }

    #pragma unroll
    for (int j = 0; j < 4; j++) {
        int kl = ty * 4 + j;
        tile[kl][tx] = W[(size_t)(kb + kl) * DFC + nb + tx];
    }
    __syncthreads();
    #pragma unroll
    for (int j = 0; j < 4; j++) {
        int nl = ty * 4 + j;
        float v = tile[tx][nl];
        __nv_bfloat16 h = __float2bfloat16(v);
        size_t o = (size_t)(nb + nl) * DFC + kb + tx;
        hi[o] = h;
        lo[o] = __float2bfloat16(v - __bfloat162float(h));
    }
}

// ---------------- K5: persistent mma.sync bf16-split GEMM (R11 version) -----
// CTA tile 128x128, BK=64, 3 stages, 8 warps, 2 CTA/SM; tiles via atomic ctr.
#define SASTRIDE 72
#define NSTG 3
#define STG_ELEMS (128 * SASTRIDE)
#define GEMM_DSMEM (NSTG * STG_ELEMS * 2 * 2)     // 110592 bytes
#define GEMM_CTAS 296

__global__ __launch_bounds__(256, 2) void k_gemm(
        const __nv_bfloat16* __restrict__ Ahi,
        const __nv_bfloat16* __restrict__ Alo,
        const __nv_bfloat16* __restrict__ Bhi,
        const __nv_bfloat16* __restrict__ Blo,
        const float* __restrict__ bias,
        __nv_bfloat16* __restrict__ OutHi,
        __nv_bfloat16* __restrict__ OutLo,
        float* __restrict__ OutF,
        const float* __restrict__ w3,
        float* __restrict__ part,
        int mode, int ctri, int kdim, int cpsShift, int nxShift, int ntiles) {
    extern __shared__ __align__(16) __nv_bfloat16 dsm[];
    __nv_bfloat16* sAbase = dsm;
    __nv_bfloat16* sBbase = dsm + NSTG * STG_ELEMS;
    __shared__ int s_tile;

    const int t = threadIdx.x;
    const int wid = t >> 5, lane = t & 31;
    const int wm = wid >> 1, wn = wid & 1;        // warp grid 4x2
    unsigned int* ctr = &g_tilectr[ctri];
    const int nk = 3 << cpsShift;
    const int kcMask = (1 << cpsShift) - 1;
    const int nxMask = (1 << nxShift) - 1;

    const uint32_t sAu = smem_u32(sAbase);
    const uint32_t sBu = smem_u32(sBbase);
    const int aRowSel = wm * 32 + (lane & 15);
    const int aColSel = (lane >> 4) * 8;
    const int bRowSel = wn * 64 + (lane & 7) + ((lane >> 4) << 3);
    const int bColSel = ((lane >> 3) & 1) * 8;
    const int q = lane >> 2;
    const int rr = (lane & 3) * 2;

    for (;;) {
        if (t == 0) s_tile = (int)atomicAdd(ctr, 1u);
        __syncthreads();
        const int tile = s_tile;
        if (tile >= ntiles) break;
        const int bm = (tile >> nxShift) * 128;
        const int bn = (tile & nxMask) * 128;

        float acc[2][8][4];
        #pragma unroll
        for (int i = 0; i < 2; i++)
            #pragma unroll
            for (int j = 0; j < 8; j++)
                #pragma unroll
                for (int qq = 0; qq < 4; qq++) acc[i][j][qq] = 0.0f;

        auto load_stage = [&](int i, int s) {
            const int split = i >> cpsShift;
            const int kc = i & kcMask;
            const __nv_bfloat16* As = (split == 2) ? Alo : Ahi;
            const __nv_bfloat16* Bs = (split == 1) ? Blo : Bhi;
            #pragma unroll
            for (int p = 0; p < 4; p++) {
                int e = t + p * 256;
                int row = e >> 3, cg = (e & 7) * 8;
                cp16(sAu + (uint32_t)(s * STG_ELEMS + row * SASTRIDE + cg) * 2,
                     As + (size_t)(bm + row) * kdim + kc * 64 + cg);
                cp16(sBu + (uint32_t)(s * STG_ELEMS + row * SASTRIDE + cg) * 2,
                     Bs + (size_t)(bn + row) * kdim + kc * 64 + cg);
            }
        };

        #pragma unroll
        for (int p = 0; p < NSTG - 1; p++) {
            load_stage(p, p);
            CP_COMMIT();
        }

        int stg = 0;
        for (int i = 0; i < nk; i++) {
            CP_WAIT(NSTG - 2);
            __syncthreads();

            const uint32_t aBase = sAu + (uint32_t)(stg * STG_ELEMS) * 2;
            const uint32_t bBase = sBu + (uint32_t)(stg * STG_ELEMS) * 2;
            #pragma unroll
            for (int kk = 0; kk < 64; kk += 16) {
                uint32_t afr[2][4];
                #pragma unroll
                for (int mi = 0; mi < 2; mi++)
                    ldm_x4(afr[mi],
                           aBase + (uint32_t)((aRowSel + mi * 16) * SASTRIDE
                                              + kk + aColSel) * 2);
                uint32_t bfr[4][4];
                #pragma unroll
                for (int np = 0; np < 4; np++)
                    ldm_x4(bfr[np],
                           bBase + (uint32_t)((bRowSel + np * 16) * SASTRIDE
                                              + kk + bColSel) * 2);
                #pragma unroll
                for (int mi = 0; mi < 2; mi++)
                    #pragma unroll
                    for (int np = 0; np < 4; np++) {
                        mma16816(acc[mi][np * 2 + 0], afr[mi], &bfr[np][0]);
                        mma16816(acc[mi][np * 2 + 1], afr[mi], &bfr[np][2]);
                    }
            }
            if (i + NSTG - 1 < nk) {
                int s2 = i + NSTG - 1;
                load_stage(s2, s2 % NSTG);
            }
            CP_COMMIT();
            if (++stg == NSTG) stg = 0;
        }
        CP_WAIT(0);
        __syncthreads();

        // ---------------- epilogue ----------------
        if (mode == 0) {
            #pragma unroll
            for (int mi = 0; mi < 2; mi++) {
                #pragma unroll
                for (int ni = 0; ni < 8; ni++) {
                    int col = bn + wn * 64 + ni * 8 + rr;
                    float b0 = bias[col], b1 = bias[col + 1];
                    #pragma unroll
                    for (int h = 0; h < 2; h++) {
                        int row = bm + wm * 32 + mi * 16 + q + h * 8;
                        float v0 = fmaxf(acc[mi][ni][h * 2 + 0] + b0, 0.0f);
                        float v1 = fmaxf(acc[mi][ni][h * 2 + 1] + b1, 0.0f);
                        __nv_bfloat16 h0 = __float2bfloat16(v0);
                        __nv_bfloat16 h1 = __float2bfloat16(v1);
                        __nv_bfloat162 hp; hp.x = h0; hp.y = h1;
                        __nv_bfloat162 lp;
                        lp.x = __float2bfloat16(v0 - __bfloat162float(h0));
                        lp.y = __float2bfloat16(v1 - __bfloat162float(h1));
                        size_t o = (size_t)row * DFC + col;
                        *(__nv_bfloat162*)(OutHi + o) = hp;
                        *(__nv_bfloat162*)(OutLo + o) = lp;
                    }
                }
            }
        } else if (mode == 2) {
            #pragma unroll
            for (int mi = 0; mi < 2; mi++) {
                #pragma unroll
                for (int ni = 0; ni < 8; ni++) {
                    int col = bn + wn * 64 + ni * 8 + rr;
                    float b0 = bias[col], b1 = bias[col + 1];
                    #pragma unroll
                    for (int h = 0; h < 2; h++) {
                        int row = bm + wm * 32 + mi * 16 + q + h * 8;
                        float2 o2;
                        o2.x = acc[mi][ni][h * 2 + 0] + b0;
                        o2.y = acc[mi][ni][h * 2 + 1] + b1;
                        *(float2*)(OutF + (size_t)row * DLOI + col) = o2;
                    }
                }
            }
        } else {
            float* ps = (float*)dsm;               // [8][32]
            #pragma unroll
            for (int mi = 0; mi < 2; mi++) {
                float p0 = 0.0f, p1 = 0.0f;
                #pragma unroll
                for (int ni = 0; ni < 8; ni++) {
                    int col = bn + wn * 64 + ni * 8 + rr;
                    float b0 = bias[col], b1 = bias[col + 1];
                    float w0 = w3[col], w1 = w3[col + 1];
                    p0 += fmaxf(acc[mi][ni][0] + b0, 0.0f) * w0
                        + fmaxf(acc[mi][ni][1] + b1, 0.0f) * w1;
                    p1 += fmaxf(acc[mi][ni][2] + b0, 0.0f) * w0
                        + fmaxf(acc[mi][ni][3] + b1, 0.0f) * w1;
                }
                p0 += __shfl_xor_sync(0xffffffffu, p0, 1);
                p0 += __shfl_xor_sync(0xffffffffu, p0, 2);
                p1 += __shfl_xor_sync(0xffffffffu, p1, 1);
                p1 += __shfl_xor_sync(0xffffffffu, p1, 2);
                if ((lane & 3) == 0) {
                    ps[wid * 32 + mi * 16 + q] = p0;
                    ps[wid * 32 + mi * 16 + 8 + q] = p1;
                }
            }
            __syncthreads();
            if (t < 128) {
                int rw = t >> 5, rl = t & 31;
                float tot = ps[(rw * 2 + 0) * 32 + rl]
                          + ps[(rw * 2 + 1) * 32 + rl];
                part[(size_t)(bm + t) * 8 + (tile & nxMask)] = tot;
            }
        }
        __syncthreads();
    }
}

// ---------------- K6: scores + labels + lines (fused) -----------------------
__global__ void k_out(const float* __restrict__ b3, float* __restrict__ out) {
    const int gp = blockIdx.x * 256 + threadIdx.x;
    if (gp >= NROWS) return;
    const float* pp = g_part + (size_t)gp * 8;
    float s = pp[0] + pp[1] + pp[2] + pp[3] + pp[4] + pp[5] + pp[6] + pp[7];
    out[gp] = s + b3[0];
    out[NROWS + gp] = 0.0f;
    const int b = gp / NPAIR;
    const int p = gp - b * NPAIR;
    int u, v;
    pair_uv(p, u, v);
    float* L = out + 2 * NROWS + (size_t)gp * 4;
    L[0] = g_xy[b][u][0];
    L[1] = g_xy[b][u][1];
    L[2] = g_xy[b][v][0];
    L[3] = g_xy[b][v][1];
}

// ---------------- launch -----------------------------------------------------
extern "C" void kernel_launch(void* const* d_in, const int* in_sizes, int n_in,
                              void* d_out, int out_size) {
    const float* inputs   = (const float*)d_in[0];
    const float* features = (const float*)d_in[1];
    const float* fc1_w    = (const float*)d_in[2];
    const float* fc1_b    = (const float*)d_in[3];
    const float* w1       = (const float*)d_in[4];
    const float* b1       = (const float*)d_in[5];
    const float* w2       = (const float*)d_in[6];
    const float* b2       = (const float*)d_in[7];
    const float* w3       = (const float*)d_in[8];
    const float* b3       = (const float*)d_in[9];
    float* out = (float*)d_out;

    void *pxf, *pfth, *pftl, *pfch, *pfcl;
    void *pxvh, *pxvl, *ph1h, *ph1l, *pw1h, *pw1l, *pw2h, *pw2l, *ppart;
    cudaGetSymbolAddress(&pxf, g_xf);
    cudaGetSymbolAddress(&pfth, g_ft_hi);
    cudaGetSymbolAddress(&pftl, g_ft_lo);
    cudaGetSymbolAddress(&pfch, g_fc_hi);
    cudaGetSymbolAddress(&pfcl, g_fc_lo);
    cudaGetSymbolAddress(&pxvh, g_xv_hi);
    cudaGetSymbolAddress(&pxvl, g_xv_lo);
    cudaGetSymbolAddress(&ph1h, g_h1_hi);
    cudaGetSymbolAddress(&ph1l, g_h1_lo);
    cudaGetSymbolAddress(&pw1h, g_w1t_hi);
    cudaGetSymbolAddress(&pw1l, g_w1t_lo);
    cudaGetSymbolAddress(&pw2h, g_w2t_hi);
    cudaGetSymbolAddress(&pw2l, g_w2t_lo);
    cudaGetSymbolAddress(&ppart, g_part);

    const size_t topk_smem = (size_t)NPIX * 2 * 4 + 512 * 8 + 256 * 4 + 64;
    cudaFuncSetAttribute(k_topk, cudaFuncAttributeMaxDynamicSharedMemorySize,
                         (int)topk_smem);
    cudaFuncSetAttribute(k_gemm, cudaFuncAttributeMaxDynamicSharedMemorySize,
                         GEMM_DSMEM);

    k_wsplit<<<dim3(32, 32, 2), 256>>>(w1, w2);
    k_ftsplit<<<dim3(NPIX / 32, 8, BATCH), 256>>>(features);
    k_fsplit<<<(DLOI * 256 + 255) / 256, 256>>>(fc1_w);

    // xf = features^T @ fc1_w^T + fc1_b   (M=32768, N=128, K=256), fp32 out
    k_gemm<<<GEMM_CTAS, 256, GEMM_DSMEM>>>(
        (const __nv_bfloat16*)pfth, (const __nv_bfloat16*)pftl,
        (const __nv_bfloat16*)pfch, (const __nv_bfloat16*)pfcl,
        fc1_b, nullptr, nullptr, (float*)pxf, nullptr, nullptr,
        2, 0, 256, 2, 0, MPIX / 128);

    k_topk<<<BATCH, 512, topk_smem>>>(inputs);
    k_pool<<<NROWS, 128>>>();

    k_gemm<<<GEMM_CTAS, 256, GEMM_DSMEM>>>(
        (const __nv_bfloat16*)pxvh, (const __nv_bfloat16*)pxvl,
        (const __nv_bfloat16*)pw1h, (const __nv_bfloat16*)pw1l,
        b1, (__nv_bfloat16*)ph1h, (__nv_bfloat16*)ph1l, nullptr,
        nullptr, nullptr, 0, 1, DFC, 4, 3, 8 * (NROWS / 128));
    k_gemm<<<GEMM_CTAS, 256, GEMM_DSMEM>>>(
        (const __nv_bfloat16*)ph1h, (const __nv_bfloat16*)ph1l,
        (const __nv_bfloat16*)pw2h, (const __nv_bfloat16*)pw2l,
        b2, nullptr, nullptr, nullptr,
        w3, (float*)ppart, 1, 2, DFC, 4, 3, 8 * (NROWS / 128));

    k_out<<<(NROWS + 255) / 256, 256>>>(b3, out);
}

// round 16
// speedup vs baseline: 1.2063x; 1.0106x over previous
#include <cuda_runtime.h>
#include <cuda_bf16.h>
#include <math.h>
#include <stdint.h>

#define HW 128
#define NPIX 16384
#define BATCH 2
#define KJ 128
#define NPAIR 8128
#define NROWS (BATCH * NPAIR)   // 16256
#define DLOI 128
#define DFC 1024
#define MPIX (BATCH * NPIX)     // 32768

// ---------------- scratch (device globals; no allocations allowed) ----------
__device__ float g_xf[(size_t)MPIX * DLOI];   // (b*pix, d)
__device__ float g_xy[BATCH][KJ][2];
__device__ __align__(16) __nv_bfloat16 g_ft_hi[(size_t)MPIX * 256];
__device__ __align__(16) __nv_bfloat16 g_ft_lo[(size_t)MPIX * 256];
__device__ __align__(16) __nv_bfloat16 g_fc_hi[DLOI * 256];
__device__ __align__(16) __nv_bfloat16 g_fc_lo[DLOI * 256];
__device__ __align__(16) __nv_bfloat16 g_xv_hi[(size_t)NROWS * DFC];
__device__ __align__(16) __nv_bfloat16 g_xv_lo[(size_t)NROWS * DFC];
__device__ __align__(16) __nv_bfloat16 g_h1_hi[(size_t)NROWS * DFC];
__device__ __align__(16) __nv_bfloat16 g_h1_lo[(size_t)NROWS * DFC];
__device__ __align__(16) __nv_bfloat16 g_w1t_hi[DFC * DFC];
__device__ __align__(16) __nv_bfloat16 g_w1t_lo[DFC * DFC];
__device__ __align__(16) __nv_bfloat16 g_w2t_hi[DFC * DFC];
__device__ __align__(16) __nv_bfloat16 g_w2t_lo[DFC * DFC];
__device__ float g_part[(size_t)NROWS * 8];
__device__ unsigned int g_tilectr[3];

// ---------------- helpers ----------------------------------------------------
__device__ __forceinline__ uint32_t smem_u32(const void* p) {
    uint32_t a;
    asm("{ .reg .u64 t; cvta.to.shared.u64 t, %1; cvt.u32.u64 %0, t; }"
        : "=r"(a) : "l"(p));
    return a;
}
__device__ __forceinline__ void cp16(uint32_t s, const void* g) {
    asm volatile("cp.async.cg.shared.global [%0], [%1], 16;"
                 :: "r"(s), "l"(g) : "memory");
}
#define CP_COMMIT() asm volatile("cp.async.commit_group;" ::: "memory")
#define CP_WAIT(n)  asm volatile("cp.async.wait_group %0;" :: "n"(n) : "memory")

__device__ __forceinline__ void ldm_x4(uint32_t* r, uint32_t addr) {
    asm volatile("ldmatrix.sync.aligned.m8n8.x4.shared.b16 {%0,%1,%2,%3}, [%4];"
                 : "=r"(r[0]), "=r"(r[1]), "=r"(r[2]), "=r"(r[3]) : "r"(addr));
}
__device__ __forceinline__ void mma16816(float* c, const uint32_t* a,
                                         const uint32_t* b) {
    asm volatile(
        "mma.sync.aligned.m16n8k16.row.col.f32.bf16.bf16.f32 "
        "{%0,%1,%2,%3}, {%4,%5,%6,%7}, {%8,%9}, {%0,%1,%2,%3};"
        : "+f"(c[0]), "+f"(c[1]), "+f"(c[2]), "+f"(c[3])
        : "r"(a[0]), "r"(a[1]), "r"(a[2]), "r"(a[3]), "r"(b[0]), "r"(b[1]));
}

// ---------------- pair index helpers (triu_indices(K=128, k=1)) -------------
__device__ __forceinline__ int pair_off(int u) { return u * (255 - u) / 2; }
__device__ __forceinline__ void pair_uv(int p, int& u, int& v) {
    int uu = (int)((255.0 - sqrt(255.0 * 255.0 - 8.0 * (double)p)) * 0.5);
    if (uu < 0) uu = 0;
    if (uu > 126) uu = 126;
    while (uu < 126 && pair_off(uu + 1) <= p) uu++;
    while (uu > 0 && pair_off(uu) > p) uu--;
    u = uu;
    v = uu + 1 + (p - pair_off(uu));
}

// ---------------- K1: jmap + NMS + radix-select top-128 ---------------------
// Exact top_k semantics: value desc, index asc tie-break (bits of floats >= 0
// order identically to values; key = ~((bits<<32)|(NPIX-1-idx)) asc-sorted).
__global__ void k_topk(const float* __restrict__ inputs) {
    extern __shared__ float sh[];
    float* smap = sh;                                      // NPIX
    float* nmsv = smap + NPIX;                             // NPIX
    unsigned long long* keys = (unsigned long long*)(nmsv + NPIX);  // 512
    unsigned int* hist = (unsigned int*)(keys + 512);      // 256
    unsigned int* ctrl = hist + 256;                       // 4

    const int b = blockIdx.x;
    const int t = threadIdx.x;
    const float* in0 = inputs + (size_t)b * 5 * NPIX;
    const float* in1 = in0 + NPIX;

    for (int i = t; i < NPIX; i += 512) {
        float x0 = in0[i], x1 = in1[i];
        float m = fmaxf(x0, x1);
        float e0 = expf(x0 - m), e1 = expf(x1 - m);
        smap[i] = e1 / (e0 + e1);
    }
    if (t == 0) { ctrl[0] = 0; ctrl[1] = KJ; ctrl[2] = 0; }
    __syncthreads();

    for (int jj = 0; jj < 32; jj++) {
        int idx = t * 32 + jj;
        int y = idx >> 7, x = idx & 127;
        float v = smap[idx];
        float m = v;
        #pragma unroll
        for (int dy = -1; dy <= 1; dy++) {
            int yy = y + dy;
            if (yy < 0 || yy >= HW) continue;
            #pragma unroll
            for (int dx = -1; dx <= 1; dx++) {
                int xx = x + dx;
                if (xx < 0 || xx >= HW) continue;
                m = fmaxf(m, smap[yy * HW + xx]);
            }
        }
        nmsv[idx] = (v == m) ? v : 0.0f;
    }
    __syncthreads();

    // 4-pass radix: find exact 128th-largest bit pattern T
    #pragma unroll
    for (int pass = 0; pass < 4; pass++) {
        const int shift = 24 - 8 * pass;
        if (t < 256) hist[t] = 0;
        __syncthreads();
        unsigned int prefix = ctrl[0];
        unsigned int himask = (pass == 0) ? 0u : (0xFFFFFFFFu << (shift + 8));
        for (int i = t; i < NPIX; i += 512) {
            unsigned int bits = __float_as_uint(nmsv[i]);
            if ((bits & himask) == prefix)
                atomicAdd(&hist[(bits >> shift) & 0xFF], 1u);
        }
        __syncthreads();
        if (t == 0) {
            unsigned int need = ctrl[1];
            int bsel = 0;
            for (int bb = 255; bb >= 0; bb--) {
                unsigned int c = hist[bb];
                if (c < need) need -= c;
                else { bsel = bb; break; }
            }
            ctrl[0] = prefix | ((unsigned int)bsel << shift);
            ctrl[1] = need;
        }
        __syncthreads();
    }

    const unsigned int T = ctrl[0];
    for (int i = t; i < NPIX; i += 512) {
        unsigned int bits = __float_as_uint(nmsv[i]);
        if (bits >= T) {
            unsigned int slot = atomicAdd(&ctrl[2], 1u);
            if (slot < 512)
                keys[slot] = ~(((unsigned long long)bits << 32)
                               | (unsigned long long)(unsigned int)(NPIX - 1 - i));
        }
    }
    __syncthreads();
    const unsigned int m = ctrl[2] > 512u ? 512u : ctrl[2];
    if ((unsigned int)t >= m) keys[t] = ~0ULL;   // pad sorts last
    __syncthreads();

    // bitonic ascending sort of 512 inverted keys (thread t owns slot t)
    for (int k = 2; k <= 512; k <<= 1) {
        for (int j = k >> 1; j > 0; j >>= 1) {
            int ixj = t ^ j;
            if (ixj > t) {
                bool asc = ((t & k) == 0);
                unsigned long long a = keys[t], c = keys[ixj];
                if ((a > c) == asc) { keys[t] = c; keys[ixj] = a; }
            }
            __syncthreads();
        }
    }

    if (t < KJ) {
        unsigned long long key = ~keys[t];
        int idx = NPIX - 1 - (int)(unsigned int)(key & 0xFFFFFFFFu);
        const float* in3 = in0 + 3 * NPIX;
        const float* in4 = in0 + 4 * NPIX;
        float sy = 1.0f / (1.0f + expf(-in3[idx]));
        float sx = 1.0f / (1.0f + expf(-in4[idx]));
        g_xy[b][t][0] = (float)(idx >> 7) + sy;
        g_xy[b][t][1] = (float)(idx & 127) + sx;
    }
}

// ---------------- K2a: transpose+split features (c,pix)->(pix,c) bf16 -------
__global__ __launch_bounds__(256) void k_ftsplit(const float* __restrict__ F) {
    __shared__ float tile[32][33];
    const int tx = threadIdx.x & 31;
    const int ty = threadIdx.x >> 5;
    const int pixb = blockIdx.x * 32;
    const int cb = blockIdx.y * 32;
    const int b = blockIdx.z;
    const float* src = F + (size_t)b * 256 * NPIX;
    #pragma unroll
    for (int j = 0; j < 4; j++) {
        int cl = ty * 4 + j;
        tile[cl][tx] = src[(size_t)(cb + cl) * NPIX + pixb + tx];
    }
    __syncthreads();
    #pragma unroll
    for (int j = 0; j < 4; j++) {
        int pl = ty * 4 + j;
        float v = tile[tx][pl];
        __nv_bfloat16 h = __float2bfloat16(v);
        size_t o = ((size_t)b * NPIX + pixb + pl) * 256 + cb + tx;
        g_ft_hi[o] = h;
        g_ft_lo[o] = __float2bfloat16(v - __bfloat162float(h));
    }
}

// ---------------- K2b: split fc1_w (already (N=128,K=256) K-contig) ---------
__global__ void k_fsplit(const float* __restrict__ W) {
    int i = blockIdx.x * 256 + threadIdx.x;
    if (i < DLOI * 256) {
        float v = W[i];
        __nv_bfloat16 h = __float2bfloat16(v);
        g_fc_hi[i] = h;
        g_fc_lo[i] = __float2bfloat16(v - __bfloat162float(h));
    }
}

// ---------------- K3: LOI pool (float4 gathers) --> xv bf16 hi/lo -----------
__global__ __launch_bounds__(128) void k_pool() {
    const int gp = blockIdx.x;
    const int b = gp / NPAIR;
    const int p = gp - b * NPAIR;
    const int t = threadIdx.x;

    __shared__ __align__(16) int   s_o[32][4];
    __shared__ __align__(16) float s_w[32][4];
    __shared__ __align__(16) float stage2[8 * 132];

    if (t < 32) {
        int u, v;
        pair_uv(p, u, v);
        const float yu = g_xy[b][u][0], xu = g_xy[b][u][1];
        const float yv = g_xy[b][v][0], xv = g_xy[b][v][1];
        const int j = t;
        float lam = (float)j / 31.0f;
        float oml = 1.0f - lam;
        float fy = yu * lam + yv * oml - 0.5f;
        float fx = xu * lam + xv * oml - 0.5f;
        float y0f = fminf(fmaxf(floorf(fy), 0.0f), 127.0f);
        float x0f = fminf(fmaxf(floorf(fx), 0.0f), 127.0f);
        float y1f = fminf(y0f + 1.0f, 127.0f);
        float x1f = fminf(x0f + 1.0f, 127.0f);
        int y0 = (int)y0f, x0 = (int)x0f, y1 = (int)y1f, x1 = (int)x1f;
        float wy0 = fy - y0f, wy1 = y1f - fy;
        float wx0 = fx - x0f, wx1 = x1f - fx;
        s_o[j][0] = (y0 * HW + x0) * DLOI;
        s_o[j][1] = (y1 * HW + x0) * DLOI;
        s_o[j][2] = (y0 * HW + x1) * DLOI;
        s_o[j][3] = (y1 * HW + x1) * DLOI;
        s_w[j][0] = wy1 * wx1;
        s_w[j][1] = wy0 * wx1;
        s_w[j][2] = wy1 * wx0;
        s_w[j][3] = wy0 * wx0;
    }
    __syncthreads();

    const int cg = t & 31;
    const int jg = t >> 5;
    const float* xfb = g_xf + (size_t)b * NPIX * DLOI + cg * 4;

    float4 gm = make_float4(-INFINITY, -INFINITY, -INFINITY, -INFINITY);
    #pragma unroll
    for (int jj = 0; jj < 8; jj++) {
        int j = jg * 8 + jj;
        int4  o = *(const int4*)s_o[j];
        float4 w = *(const float4*)s_w[j];
        float4 c0 = *(const float4*)(xfb + o.x);
        float4 c1 = *(const float4*)(xfb + o.y);
        float4 c2 = *(const float4*)(xfb + o.z);
        float4 c3 = *(const float4*)(xfb + o.w);
        float4 v;
        v.x = c0.x * w.x + c1.x * w.y + c2.x * w.z + c3.x * w.w;
        v.y = c0.y * w.x + c1.y * w.y + c2.y * w.z + c3.y * w.w;
        v.z = c0.z * w.x + c1.z * w.y + c2.z * w.z + c3.z * w.w;
        v.w = c0.w * w.x + c1.w * w.y + c2.w * w.z + c3.w * w.w;
        gm.x = fmaxf(gm.x, v.x); gm.y = fmaxf(gm.y, v.y);
        gm.z = fmaxf(gm.z, v.z); gm.w = fmaxf(gm.w, v.w);
        if ((jj & 3) == 3) {
            *(float4*)&stage2[(j >> 2) * 132 + cg * 4] = gm;
            gm = make_float4(-INFINITY, -INFINITY, -INFINITY, -INFINITY);
        }
    }
    __syncthreads();

    __nv_bfloat16* oh = g_xv_hi + (size_t)gp * 1024;
    __nv_bfloat16* ol = g_xv_lo + (size_t)gp * 1024;
    #pragma unroll
    for (int i = 0; i < 8; i++) {
        int l = t + i * 128;                       // linear = c*8+g
        float s = stage2[(l & 7) * 132 + (l >> 3)];
        __nv_bfloat16 h = __float2bfloat16(s);
        oh[l] = h;
        ol[l] = __float2bfloat16(s - __bfloat162float(h));
    }
}

// ---------------- K4: transpose+split w1/w2; zero tile counters -------------
__global__ __launch_bounds__(256) void k_wsplit(const float* __restrict__ W1,
                                                const float* __restrict__ W2) {
    __shared__ float tile[32][33];
    const int tx = threadIdx.x & 31;
    const int ty = threadIdx.x >> 5;
    const int kb = blockIdx.y * 32;
    const int nb = blockIdx.x * 32;
    const int z = blockIdx.z;
    const float* W = z ? W2 : W1;
    __nv_bfloat16* hi = z ? g_w2t_hi : g_w1t_hi;
    __nv_bfloat16* lo = z ? g_w2t_lo : g_w1t_lo;

    if (z == 0 && blockIdx.x == 0 && blockIdx.y == 0 && threadIdx.x == 0) {
        g_tilectr[0] = 0;
        g_tilectr[1] = 0;
        g_tilectr[2] = 0;
    }

    #pragma unroll
    for (int j = 0; j < 4; j++) {
        int kl = ty * 4 + j;
        tile[kl][tx] = W[(size_t)(kb + kl) * DFC + nb + tx];
    }
    __syncthreads();
    #pragma unroll
    for (int j = 0; j < 4; j++) {
        int nl = ty * 4 + j;
        float v = tile[tx][nl];
        __nv_bfloat16 h = __float2bfloat16(v);
        size_t o = (size_t)(nb + nl) * DFC + kb + tx;
        hi[o] = h;
        lo[o] = __float2bfloat16(v - __bfloat162float(h));
    }
}

// ---------------- K5: persistent mma.sync bf16-split GEMM (R11 version) -----
// CTA tile 128x128, BK=64, 3 stages, 8 warps, 2 CTA/SM; tiles via atomic ctr.
#define SASTRIDE 72
#define NSTG 3
#define STG_ELEMS (128 * SASTRIDE)
#define GEMM_DSMEM (NSTG * STG_ELEMS * 2 * 2)     // 110592 bytes
#define GEMM_CTAS 296

__global__ __launch_bounds__(256, 2) void k_gemm(
        const __nv_bfloat16* __restrict__ Ahi,
        const __nv_bfloat16* __restrict__ Alo,
        const __nv_bfloat16* __restrict__ Bhi,
        const __nv_bfloat16* __restrict__ Blo,
        const float* __restrict__ bias,
        __nv_bfloat16* __restrict__ OutHi,
        __nv_bfloat16* __restrict__ OutLo,
        float* __restrict__ OutF,
        const float* __restrict__ w3,
        float* __restrict__ part,
        int mode, int ctri, int kdim, int cpsShift, int nxShift, int ntiles) {
    extern __shared__ __align__(16) __nv_bfloat16 dsm[];
    __nv_bfloat16* sAbase = dsm;
    __nv_bfloat16* sBbase = dsm + NSTG * STG_ELEMS;
    __shared__ int s_tile;

    const int t = threadIdx.x;
    const int wid = t >> 5, lane = t & 31;
    const int wm = wid >> 1, wn = wid & 1;        // warp grid 4x2
    unsigned int* ctr = &g_tilectr[ctri];
    const int nk = 3 << cpsShift;
    const int kcMask = (1 << cpsShift) - 1;
    const int nxMask = (1 << nxShift) - 1;

    const uint32_t sAu = smem_u32(sAbase);
    const uint32_t sBu = smem_u32(sBbase);
    const int aRowSel = wm * 32 + (lane & 15);
    const int aColSel = (lane >> 4) * 8;
    const int bRowSel = wn * 64 + (lane & 7) + ((lane >> 4) << 3);
    const int bColSel = ((lane >> 3) & 1) * 8;
    const int q = lane >> 2;
    const int rr = (lane & 3) * 2;

    for (;;) {
        if (t == 0) s_tile = (int)atomicAdd(ctr, 1u);
        __syncthreads();
        const int tile = s_tile;
        if (tile >= ntiles) break;
        const int bm = (tile >> nxShift) * 128;
        const int bn = (tile & nxMask) * 128;

        float acc[2][8][4];
        #pragma unroll
        for (int i = 0; i < 2; i++)
            #pragma unroll
            for (int j = 0; j < 8; j++)
                #pragma unroll
                for (int qq = 0; qq < 4; qq++) acc[i][j][qq] = 0.0f;

        auto load_stage = [&](int i, int s) {
            const int split = i >> cpsShift;
            const int kc = i & kcMask;
            const __nv_bfloat16* As = (split == 2) ? Alo : Ahi;
            const __nv_bfloat16* Bs = (split == 1) ? Blo : Bhi;
            #pragma unroll
            for (int p = 0; p < 4; p++) {
                int e = t + p * 256;
                int row = e >> 3, cg = (e & 7) * 8;
                cp16(sAu + (uint32_t)(s * STG_ELEMS + row * SASTRIDE + cg) * 2,
                     As + (size_t)(bm + row) * kdim + kc * 64 + cg);
                cp16(sBu + (uint32_t)(s * STG_ELEMS + row * SASTRIDE + cg) * 2,
                     Bs + (size_t)(bn + row) * kdim + kc * 64 + cg);
            }
        };

        #pragma unroll
        for (int p = 0; p < NSTG - 1; p++) {
            load_stage(p, p);
            CP_COMMIT();
        }

        int stg = 0;
        for (int i = 0; i < nk; i++) {
            CP_WAIT(NSTG - 2);
            __syncthreads();

            const uint32_t aBase = sAu + (uint32_t)(stg * STG_ELEMS) * 2;
            const uint32_t bBase = sBu + (uint32_t)(stg * STG_ELEMS) * 2;
            #pragma unroll
            for (int kk = 0; kk < 64; kk += 16) {
                uint32_t afr[2][4];
                #pragma unroll
                for (int mi = 0; mi < 2; mi++)
                    ldm_x4(afr[mi],
                           aBase + (uint32_t)((aRowSel + mi * 16) * SASTRIDE
                                              + kk + aColSel) * 2);
                uint32_t bfr[4][4];
                #pragma unroll
                for (int np = 0; np < 4; np++)
                    ldm_x4(bfr[np],
                           bBase + (uint32_t)((bRowSel + np * 16) * SASTRIDE
                                              + kk + bColSel) * 2);
                #pragma unroll
                for (int mi = 0; mi < 2; mi++)
                    #pragma unroll
                    for (int np = 0; np < 4; np++) {
                        mma16816(acc[mi][np * 2 + 0], afr[mi], &bfr[np][0]);
                        mma16816(acc[mi][np * 2 + 1], afr[mi], &bfr[np][2]);
                    }
            }
            if (i + NSTG - 1 < nk) {
                int s2 = i + NSTG - 1;
                load_stage(s2, s2 % NSTG);
            }
            CP_COMMIT();
            if (++stg == NSTG) stg = 0;
        }
        CP_WAIT(0);
        __syncthreads();

        // ---------------- epilogue ----------------
        if (mode == 0) {
            #pragma unroll
            for (int mi = 0; mi < 2; mi++) {
                #pragma unroll
                for (int ni = 0; ni < 8; ni++) {
                    int col = bn + wn * 64 + ni * 8 + rr;
                    float b0 = bias[col], b1 = bias[col + 1];
                    #pragma unroll
                    for (int h = 0; h < 2; h++) {
                        int row = bm + wm * 32 + mi * 16 + q + h * 8;
                        float v0 = fmaxf(acc[mi][ni][h * 2 + 0] + b0, 0.0f);
                        float v1 = fmaxf(acc[mi][ni][h * 2 + 1] + b1, 0.0f);
                        __nv_bfloat16 h0 = __float2bfloat16(v0);
                        __nv_bfloat16 h1 = __float2bfloat16(v1);
                        __nv_bfloat162 hp; hp.x = h0; hp.y = h1;
                        __nv_bfloat162 lp;
                        lp.x = __float2bfloat16(v0 - __bfloat162float(h0));
                        lp.y = __float2bfloat16(v1 - __bfloat162float(h1));
                        size_t o = (size_t)row * DFC + col;
                        *(__nv_bfloat162*)(OutHi + o) = hp;
                        *(__nv_bfloat162*)(OutLo + o) = lp;
                    }
                }
            }
        } else if (mode == 2) {
            #pragma unroll
            for (int mi = 0; mi < 2; mi++) {
                #pragma unroll
                for (int ni = 0; ni < 8; ni++) {
                    int col = bn + wn * 64 + ni * 8 + rr;
                    float b0 = bias[col], b1 = bias[col + 1];
                    #pragma unroll
                    for (int h = 0; h < 2; h++) {
                        int row = bm + wm * 32 + mi * 16 + q + h * 8;
                        float2 o2;
                        o2.x = acc[mi][ni][h * 2 + 0] + b0;
                        o2.y = acc[mi][ni][h * 2 + 1] + b1;
                        *(float2*)(OutF + (size_t)row * DLOI + col) = o2;
                    }
                }
            }
        } else {
            float* ps = (float*)dsm;               // [8][32]
            #pragma unroll
            for (int mi = 0; mi < 2; mi++) {
                float p0 = 0.0f, p1 = 0.0f;
                #pragma unroll
                for (int ni = 0; ni < 8; ni++) {
                    int col = bn + wn * 64 + ni * 8 + rr;
                    float b0 = bias[col], b1 = bias[col + 1];
                    float w0 = w3[col], w1 = w3[col + 1];
                    p0 += fmaxf(acc[mi][ni][0] + b0, 0.0f) * w0
                        + fmaxf(acc[mi][ni][1] + b1, 0.0f) * w1;
                    p1 += fmaxf(acc[mi][ni][2] + b0, 0.0f) * w0
                        + fmaxf(acc[mi][ni][3] + b1, 0.0f) * w1;
                }
                p0 += __shfl_xor_sync(0xffffffffu, p0, 1);
                p0 += __shfl_xor_sync(0xffffffffu, p0, 2);
                p1 += __shfl_xor_sync(0xffffffffu, p1, 1);
                p1 += __shfl_xor_sync(0xffffffffu, p1, 2);
                if ((lane & 3) == 0) {
                    ps[wid * 32 + mi * 16 + q] = p0;
                    ps[wid * 32 + mi * 16 + 8 + q] = p1;
                }
            }
            __syncthreads();
            if (t < 128) {
                int rw = t >> 5, rl = t & 31;
                float tot = ps[(rw * 2 + 0) * 32 + rl]
                          + ps[(rw * 2 + 1) * 32 + rl];
                part[(size_t)(bm + t) * 8 + (tile & nxMask)] = tot;
            }
        }
        __syncthreads();
    }
}

// ---------------- K6: scores + labels + lines (fused) -----------------------
__global__ void k_out(const float* __restrict__ b3, float* __restrict__ out) {
    const int gp = blockIdx.x * 256 + threadIdx.x;
    if (gp >= NROWS) return;
    const float* pp = g_part + (size_t)gp * 8;
    float s = pp[0] + pp[1] + pp[2] + pp[3] + pp[4] + pp[5] + pp[6] + pp[7];
    out[gp] = s + b3[0];
    out[NROWS + gp] = 0.0f;
    const int b = gp / NPAIR;
    const int p = gp - b * NPAIR;
    int u, v;
    pair_uv(p, u, v);
    float* L = out + 2 * NROWS + (size_t)gp * 4;
    L[0] = g_xy[b][u][0];
    L[1] = g_xy[b][u][1];
    L[2] = g_xy[b][v][0];
    L[3] = g_xy[b][v][1];
}

// ---------------- launch -----------------------------------------------------
extern "C" void kernel_launch(void* const* d_in, const int* in_sizes, int n_in,
                              void* d_out, int out_size) {
    const float* inputs   = (const float*)d_in[0];
    const float* features = (const float*)d_in[1];
    const float* fc1_w    = (const float*)d_in[2];
    const float* fc1_b    = (const float*)d_in[3];
    const float* w1       = (const float*)d_in[4];
    const float* b1       = (const float*)d_in[5];
    const float* w2       = (const float*)d_in[6];
    const float* b2       = (const float*)d_in[7];
    const float* w3       = (const float*)d_in[8];
    const float* b3       = (const float*)d_in[9];
    float* out = (float*)d_out;

    void *pxf, *pfth, *pftl, *pfch, *pfcl;
    void *pxvh, *pxvl, *ph1h, *ph1l, *pw1h, *pw1l, *pw2h, *pw2l, *ppart;
    cudaGetSymbolAddress(&pxf, g_xf);
    cudaGetSymbolAddress(&pfth, g_ft_hi);
    cudaGetSymbolAddress(&pftl, g_ft_lo);
    cudaGetSymbolAddress(&pfch, g_fc_hi);
    cudaGetSymbolAddress(&pfcl, g_fc_lo);
    cudaGetSymbolAddress(&pxvh, g_xv_hi);
    cudaGetSymbolAddress(&pxvl, g_xv_lo);
    cudaGetSymbolAddress(&ph1h, g_h1_hi);
    cudaGetSymbolAddress(&ph1l, g_h1_lo);
    cudaGetSymbolAddress(&pw1h, g_w1t_hi);
    cudaGetSymbolAddress(&pw1l, g_w1t_lo);
    cudaGetSymbolAddress(&pw2h, g_w2t_hi);
    cudaGetSymbolAddress(&pw2l, g_w2t_lo);
    cudaGetSymbolAddress(&ppart, g_part);

    const size_t topk_smem = (size_t)NPIX * 2 * 4 + 512 * 8 + 256 * 4 + 64;
    cudaFuncSetAttribute(k_topk, cudaFuncAttributeMaxDynamicSharedMemorySize,
                         (int)topk_smem);
    cudaFuncSetAttribute(k_gemm, cudaFuncAttributeMaxDynamicSharedMemorySize,
                         GEMM_DSMEM);

    k_wsplit<<<dim3(32, 32, 2), 256>>>(w1, w2);
    k_ftsplit<<<dim3(NPIX / 32, 8, BATCH), 256>>>(features);
    k_fsplit<<<(DLOI * 256 + 255) / 256, 256>>>(fc1_w);

    // xf = features^T @ fc1_w^T + fc1_b   (M=32768, N=128, K=256), fp32 out
    k_gemm<<<GEMM_CTAS, 256, GEMM_DSMEM>>>(
        (const __nv_bfloat16*)pfth, (const __nv_bfloat16*)pftl,
        (const __nv_bfloat16*)pfch, (const __nv_bfloat16*)pfcl,
        fc1_b, nullptr, nullptr, (float*)pxf, nullptr, nullptr,
        2, 0, 256, 2, 0, MPIX / 128);

    k_topk<<<BATCH, 512, topk_smem>>>(inputs);
    k_pool<<<NROWS, 128>>>();

    k_gemm<<<GEMM_CTAS, 256, GEMM_DSMEM>>>(
        (const __nv_bfloat16*)pxvh, (const __nv_bfloat16*)pxvl,
        (const __nv_bfloat16*)pw1h, (const __nv_bfloat16*)pw1l,
        b1, (__nv_bfloat16*)ph1h, (__nv_bfloat16*)ph1l, nullptr,
        nullptr, nullptr, 0, 1, DFC, 4, 3, 8 * (NROWS / 128));
    k_gemm<<<GEMM_CTAS, 256, GEMM_DSMEM>>>(
        (const __nv_bfloat16*)ph1h, (const __nv_bfloat16*)ph1l,
        (const __nv_bfloat16*)pw2h, (const __nv_bfloat16*)pw2l,
        b2, nullptr, nullptr, nullptr,
        w3, (float*)ppart, 1, 2, DFC, 4, 3, 8 * (NROWS / 128));

    k_out<<<(NROWS + 255) / 256, 256>>>(b3, out);
}